// round 8
// baseline (speedup 1.0000x reference)
#include <cuda_runtime.h>
#include <cuda_fp16.h>

#define FULLMASK 0xffffffffu

// ---------------- problem constants ----------------
#define F_IN   1433
#define HC     128          // HEADS*HID
#define NMAXN  50000
#define EMAXE  1600000
#define KPAD   1440         // 45 * 32
#define NCHUNK 45
#define NCLS   7

// ---------------- device scratch ----------------
__device__ float g_h1pre[NMAXN * HC];          // x @ W1
__device__ float g_h1[NMAXN * HC];             // elu(agg + b1)
__device__ float g_as1[NMAXN * 8];
__device__ float g_ad1[NMAXN * 8];
__device__ float g_h2pre[NMAXN * 8];           // h1 @ W2, padded stride 8
__device__ float g_as2[NMAXN];
__device__ float g_ad2[NMAXN];
__device__ int   g_deg[NMAXN];
__device__ int   g_off[NMAXN + 1];
__device__ int   g_cur[NMAXN];
__device__ int   g_csr[EMAXE + NMAXN];
__device__ int   g_bsum[64];
__device__ int   g_boff[64];
__device__ __half g_Wh[HC * KPAD];             // W1^T, [n][k], fp16

// ---------------- helpers ----------------
__device__ __forceinline__ void mma16816(float* c, const unsigned* a, const unsigned* b) {
    asm volatile(
        "mma.sync.aligned.m16n8k16.row.col.f32.f16.f16.f32 "
        "{%0,%1,%2,%3}, {%4,%5,%6,%7}, {%8,%9}, {%0,%1,%2,%3};"
        : "+f"(c[0]), "+f"(c[1]), "+f"(c[2]), "+f"(c[3])
        : "r"(a[0]), "r"(a[1]), "r"(a[2]), "r"(a[3]), "r"(b[0]), "r"(b[1]));
}

__device__ __forceinline__ unsigned smem_u32(const void* p) {
    unsigned a;
    asm("{ .reg .u64 t; cvta.to.shared.u64 t, %1; cvt.u32.u64 %0, t; }"
        : "=r"(a) : "l"(p));
    return a;
}

__device__ __forceinline__ void cp_async16(unsigned saddr, const void* gaddr) {
    asm volatile("cp.async.cg.shared.global [%0], [%1], 16;"
                 :: "r"(saddr), "l"(gaddr));
}
#define CP_COMMIT() asm volatile("cp.async.commit_group;" ::: "memory")
#define CP_WAIT0()  asm volatile("cp.async.wait_group 0;" ::: "memory")

__device__ __forceinline__ unsigned pack_h2(float lo, float hi) {
    __half2 h = __floats2half2_rn(lo, hi);
    return *reinterpret_cast<unsigned*>(&h);
}

// ---------------- prep: transpose W1 -> fp16 ----------------
__global__ void prep_w_kernel(const float* __restrict__ W1) {
    int idx = blockIdx.x * 256 + threadIdx.x;
    if (idx >= HC * KPAD) return;
    int n = idx / KPAD;
    int k = idx - n * KPAD;
    float v = (k < F_IN) ? W1[k * HC + n] : 0.f;
    g_Wh[idx] = __float2half_rn(v);
}

// ---------------- CSR build (edge_index is int32) ----------
__global__ void deg_init_kernel(int nn) {
    int t = blockIdx.x * 256 + threadIdx.x;
    if (t < nn) g_deg[t] = 1;  // self loop
}

__global__ void deg_count_kernel(const int* __restrict__ ei, int E, int nn) {
    int t = blockIdx.x * 256 + threadIdx.x;
    int base = t * 4;
    if (base + 3 < E) {
        int4 d = *(const int4*)(ei + E + base);
        if ((unsigned)d.x < (unsigned)nn) atomicAdd(&g_deg[d.x], 1);
        if ((unsigned)d.y < (unsigned)nn) atomicAdd(&g_deg[d.y], 1);
        if ((unsigned)d.z < (unsigned)nn) atomicAdd(&g_deg[d.z], 1);
        if ((unsigned)d.w < (unsigned)nn) atomicAdd(&g_deg[d.w], 1);
    } else {
        for (int i = base; i < E; i++) {
            int dst = ei[E + i];
            if ((unsigned)dst < (unsigned)nn) atomicAdd(&g_deg[dst], 1);
        }
    }
}

__global__ void scan1_kernel(int nn) {
    int b = blockIdx.x;
    int t = threadIdx.x;
    int idx = b * 1024 + t;
    int v = (idx < nn) ? g_deg[idx] : 0;
    int lane = t & 31, w = t >> 5;
    int s = v;
    #pragma unroll
    for (int d = 1; d < 32; d <<= 1) {
        int u = __shfl_up_sync(FULLMASK, s, d);
        if (lane >= d) s += u;
    }
    __shared__ int ws[32];
    if (lane == 31) ws[w] = s;
    __syncthreads();
    if (w == 0) {
        int x2 = ws[lane];
        #pragma unroll
        for (int d = 1; d < 32; d <<= 1) {
            int u = __shfl_up_sync(FULLMASK, x2, d);
            if (lane >= d) x2 += u;
        }
        ws[lane] = x2;
    }
    __syncthreads();
    int incl = s + ((w > 0) ? ws[w - 1] : 0);
    if (idx < nn) g_off[idx + 1] = incl;
    if (t == 1023) g_bsum[b] = incl;
}

__global__ void scan2_kernel(int nb) {
    int t = threadIdx.x;
    int v = (t < nb) ? g_bsum[t] : 0;
    int lane = t & 31, w = t >> 5;
    int s = v;
    #pragma unroll
    for (int d = 1; d < 32; d <<= 1) {
        int u = __shfl_up_sync(FULLMASK, s, d);
        if (lane >= d) s += u;
    }
    __shared__ int ws0;
    if (w == 0 && lane == 31) ws0 = s;
    __syncthreads();
    if (w == 1) s += ws0;
    if (t < 64) g_boff[t] = s - v;   // exclusive
}

__global__ void scan3_kernel(int nn) {
    int idx = blockIdx.x * 256 + threadIdx.x;
    if (idx >= nn) return;
    int add = g_boff[idx >> 10];
    int o = g_off[idx + 1] + add;
    g_off[idx + 1] = o;
    g_cur[idx] = o - g_deg[idx];
    if (idx == 0) g_off[0] = 0;
}

__global__ void scatter_kernel(const int* __restrict__ ei, int E, int nn) {
    int t = blockIdx.x * 256 + threadIdx.x;
    if (t < E) {
        int src = ei[t];
        int dst = ei[E + t];
        if ((unsigned)dst < (unsigned)nn && (unsigned)src < (unsigned)nn) {
            int pos = atomicAdd(&g_cur[dst], 1);
            g_csr[pos] = src;
        }
    } else if (t < E + nn) {
        int n = t - E;
        int pos = atomicAdd(&g_cur[n], 1);
        g_csr[pos] = n;
    }
}

// ---------------- GEMM1: h1pre = x @ W1 (fp16 HMMA, A direct from gmem) ----
// CTA tile 128x128, K-chunk 32. 8 warps, each 64x32 (warp grid 2Mx4N).
// A fragments: 8 predicated LDG.32 from x + cvt.f16x2, per (mi,kk).
// B: fp16 plane, cp.async 2-stage. Rows 40 halves (80B), conflict-free.
#define SROWH  40
#define BST    10240
#define GEMM1_SMEM (2 * BST)

__global__ void __launch_bounds__(256, 2) gemm1_kernel(
        const float* __restrict__ x,
        const float* __restrict__ att_s, const float* __restrict__ att_d,
        int n_rows) {
    extern __shared__ char smem[];
    unsigned sb = smem_u32(smem);

    int tid = threadIdx.x;
    int lane = tid & 31;
    int wid = tid >> 5;
    int m0 = blockIdx.x * 128;
    int mw = (wid & 1) * 64;
    int nw = (wid >> 1) * 32;
    int g = lane >> 2;
    int t4 = lane & 3;

    float acc[4][4][4];
    #pragma unroll
    for (int mi = 0; mi < 4; mi++)
        #pragma unroll
        for (int ni = 0; ni < 4; ni++)
            #pragma unroll
            for (int q = 0; q < 4; q++) acc[mi][ni][q] = 0.f;

    // per-mi row pointers + validity (invariant across chunks)
    const float* xr0[4];
    const float* xr1[4];
    bool rv0[4], rv1[4];
    #pragma unroll
    for (int mi = 0; mi < 4; mi++) {
        int ar = m0 + mw + mi * 16 + g;
        rv0[mi] = ar < n_rows;
        rv1[mi] = ar + 8 < n_rows;
        xr0[mi] = x + (size_t)ar * F_IN;
        xr1[mi] = x + (size_t)(ar + 8) * F_IN;
    }

    auto loadB = [&](int st, int ch) {
        unsigned base = sb + st * BST;
        int k0 = ch * 32;
        #pragma unroll
        for (int j = 0; j < 2; j++) {
            int s = tid + 256 * j;       // 0..511
            int r = s >> 2;
            int q = s & 3;
            cp_async16(base + (unsigned)(r * 80 + q * 16),
                       g_Wh + (size_t)r * KPAD + k0 + q * 8);
        }
        CP_COMMIT();
    };

    loadB(0, 0);

    auto do_chunk = [&](int ch, bool kfull) {
        int st = ch & 1;
        int k0 = ch * 32;
        CP_WAIT0();
        __syncthreads();
        if (ch + 1 < NCHUNK) loadB(st ^ 1, ch + 1);

        const __half* pB = (const __half*)(smem + st * BST);

        #pragma unroll
        for (int kk = 0; kk < 2; kk++) {
            int kcl = kk * 16 + t4 * 2;        // local col (halves)
            int kg = k0 + kcl;                 // global col
            unsigned bh[4][2];
            #pragma unroll
            for (int ni = 0; ni < 4; ni++) {
                int bn = nw + ni * 8 + g;
                bh[ni][0] = *(const unsigned*)&pB[bn * SROWH + kcl];
                bh[ni][1] = *(const unsigned*)&pB[bn * SROWH + kcl + 8];
            }
            #pragma unroll
            for (int mi = 0; mi < 4; mi++) {
                float v00, v01, v02, v03, v10, v11, v12, v13;
                if (kfull) {
                    v00 = rv0[mi] ? __ldg(xr0[mi] + kg)     : 0.f;
                    v01 = rv0[mi] ? __ldg(xr0[mi] + kg + 1) : 0.f;
                    v02 = rv0[mi] ? __ldg(xr0[mi] + kg + 8) : 0.f;
                    v03 = rv0[mi] ? __ldg(xr0[mi] + kg + 9) : 0.f;
                    v10 = rv1[mi] ? __ldg(xr1[mi] + kg)     : 0.f;
                    v11 = rv1[mi] ? __ldg(xr1[mi] + kg + 1) : 0.f;
                    v12 = rv1[mi] ? __ldg(xr1[mi] + kg + 8) : 0.f;
                    v13 = rv1[mi] ? __ldg(xr1[mi] + kg + 9) : 0.f;
                } else {
                    v00 = (rv0[mi] && kg     < F_IN) ? __ldg(xr0[mi] + kg)     : 0.f;
                    v01 = (rv0[mi] && kg + 1 < F_IN) ? __ldg(xr0[mi] + kg + 1) : 0.f;
                    v02 = (rv0[mi] && kg + 8 < F_IN) ? __ldg(xr0[mi] + kg + 8) : 0.f;
                    v03 = (rv0[mi] && kg + 9 < F_IN) ? __ldg(xr0[mi] + kg + 9) : 0.f;
                    v10 = (rv1[mi] && kg     < F_IN) ? __ldg(xr1[mi] + kg)     : 0.f;
                    v11 = (rv1[mi] && kg + 1 < F_IN) ? __ldg(xr1[mi] + kg + 1) : 0.f;
                    v12 = (rv1[mi] && kg + 8 < F_IN) ? __ldg(xr1[mi] + kg + 8) : 0.f;
                    v13 = (rv1[mi] && kg + 9 < F_IN) ? __ldg(xr1[mi] + kg + 9) : 0.f;
                }
                unsigned ah[4];
                ah[0] = pack_h2(v00, v01);
                ah[1] = pack_h2(v10, v11);
                ah[2] = pack_h2(v02, v03);
                ah[3] = pack_h2(v12, v13);
                #pragma unroll
                for (int ni = 0; ni < 4; ni++)
                    mma16816(acc[mi][ni], ah, bh[ni]);
            }
        }
    };

    for (int ch = 0; ch < NCHUNK - 1; ch++) do_chunk(ch, true);
    do_chunk(NCHUNK - 1, false);

    // ---- epilogue: store h1pre + fused att dots ----
    float2 asv[4], adv[4];
    #pragma unroll
    for (int ni = 0; ni < 4; ni++) {
        int c = nw + ni * 8 + t4 * 2;
        asv[ni] = *(const float2*)(att_s + c);
        adv[ni] = *(const float2*)(att_d + c);
    }
    int h0 = nw >> 4;

    #pragma unroll
    for (int mi = 0; mi < 4; mi++) {
        int row = m0 + mw + mi * 16 + g;
        #pragma unroll
        for (int ni = 0; ni < 4; ni++) {
            int col = nw + ni * 8 + t4 * 2;
            if (row < n_rows) {
                float2 v; v.x = acc[mi][ni][0]; v.y = acc[mi][ni][1];
                *(float2*)(g_h1pre + (size_t)row * HC + col) = v;
            }
            if (row + 8 < n_rows) {
                float2 v; v.x = acc[mi][ni][2]; v.y = acc[mi][ni][3];
                *(float2*)(g_h1pre + (size_t)(row + 8) * HC + col) = v;
            }
        }
        float psA[2] = {0.f, 0.f}, psB[2] = {0.f, 0.f};
        float pdA[2] = {0.f, 0.f}, pdB[2] = {0.f, 0.f};
        #pragma unroll
        for (int ni = 0; ni < 4; ni++) {
            int hh = ni >> 1;
            psA[hh] += acc[mi][ni][0] * asv[ni].x + acc[mi][ni][1] * asv[ni].y;
            psB[hh] += acc[mi][ni][2] * asv[ni].x + acc[mi][ni][3] * asv[ni].y;
            pdA[hh] += acc[mi][ni][0] * adv[ni].x + acc[mi][ni][1] * adv[ni].y;
            pdB[hh] += acc[mi][ni][2] * adv[ni].x + acc[mi][ni][3] * adv[ni].y;
        }
        #pragma unroll
        for (int hh = 0; hh < 2; hh++) {
            psA[hh] += __shfl_xor_sync(FULLMASK, psA[hh], 1);
            psA[hh] += __shfl_xor_sync(FULLMASK, psA[hh], 2);
            psB[hh] += __shfl_xor_sync(FULLMASK, psB[hh], 1);
            psB[hh] += __shfl_xor_sync(FULLMASK, psB[hh], 2);
            pdA[hh] += __shfl_xor_sync(FULLMASK, pdA[hh], 1);
            pdA[hh] += __shfl_xor_sync(FULLMASK, pdA[hh], 2);
            pdB[hh] += __shfl_xor_sync(FULLMASK, pdB[hh], 1);
            pdB[hh] += __shfl_xor_sync(FULLMASK, pdB[hh], 2);
        }
        if (t4 == 0) {
            if (row < n_rows) {
                g_as1[row * 8 + h0]     = psA[0];
                g_as1[row * 8 + h0 + 1] = psA[1];
                g_ad1[row * 8 + h0]     = pdA[0];
                g_ad1[row * 8 + h0 + 1] = pdA[1];
            }
            if (row + 8 < n_rows) {
                g_as1[(row + 8) * 8 + h0]     = psB[0];
                g_as1[(row + 8) * 8 + h0 + 1] = psB[1];
                g_ad1[(row + 8) * 8 + h0]     = pdB[0];
                g_ad1[(row + 8) * 8 + h0 + 1] = pdB[1];
            }
        }
    }
}

// ---------------- agg1: softmax-aggregate layer 1, + bias + ELU ----------------
__global__ void agg1_kernel(const float* __restrict__ b1, int nn) {
    int warp = (blockIdx.x * 256 + threadIdx.x) >> 5;
    int lane = threadIdx.x & 31;
    if (warp >= nn) return;
    int n = warp;
    int s0 = g_off[n], s1 = g_off[n + 1];

    float adv = (lane < 8) ? g_ad1[n * 8 + lane] : 0.f;
    float ad[8];
    #pragma unroll
    for (int h = 0; h < 8; h++) ad[h] = __shfl_sync(FULLMASK, adv, h);

    float z[8];
    #pragma unroll
    for (int h = 0; h < 8; h++) z[h] = 0.f;

    for (int i = s0 + lane; i < s1; i += 32) {
        int s = g_csr[i];
        float4 a0 = *(const float4*)(g_as1 + s * 8);
        float4 a1 = *(const float4*)(g_as1 + s * 8 + 4);
        float av[8] = {a0.x, a0.y, a0.z, a0.w, a1.x, a1.y, a1.z, a1.w};
        #pragma unroll
        for (int h = 0; h < 8; h++) {
            float t = av[h] + ad[h];
            float e = fmaxf(t, 0.2f * t);
            z[h] += __expf(e);
        }
    }
    #pragma unroll
    for (int d = 16; d; d >>= 1) {
        #pragma unroll
        for (int h = 0; h < 8; h++) z[h] += __shfl_xor_sync(FULLMASK, z[h], d);
    }
    int hme = lane >> 2;
    float izh = 1.f / z[hme];
    float adh = ad[hme];

    float4 acc = make_float4(0.f, 0.f, 0.f, 0.f);
    float4 acc2 = make_float4(0.f, 0.f, 0.f, 0.f);
    int i = s0;
    for (; i + 2 <= s1; i += 2) {
        int sA = g_csr[i], sB = g_csr[i + 1];
        float aA = __ldg(g_as1 + sA * 8 + hme);
        float aB = __ldg(g_as1 + sB * 8 + hme);
        float4 hA = *(const float4*)(g_h1pre + (size_t)sA * HC + lane * 4);
        float4 hB = *(const float4*)(g_h1pre + (size_t)sB * HC + lane * 4);
        float tA = aA + adh, tB = aB + adh;
        float eA = fmaxf(tA, 0.2f * tA), eB = fmaxf(tB, 0.2f * tB);
        float wA = __expf(eA), wB = __expf(eB);
        acc.x += wA * hA.x;  acc.y += wA * hA.y;
        acc.z += wA * hA.z;  acc.w += wA * hA.w;
        acc2.x += wB * hB.x; acc2.y += wB * hB.y;
        acc2.z += wB * hB.z; acc2.w += wB * hB.w;
    }
    if (i < s1) {
        int s = g_csr[i];
        float av = __ldg(g_as1 + s * 8 + hme);
        float tt = av + adh;
        float e = fmaxf(tt, 0.2f * tt);
        float w = __expf(e);
        float4 hv = *(const float4*)(g_h1pre + (size_t)s * HC + lane * 4);
        acc.x += w * hv.x; acc.y += w * hv.y;
        acc.z += w * hv.z; acc.w += w * hv.w;
    }
    acc.x = (acc.x + acc2.x) * izh;
    acc.y = (acc.y + acc2.y) * izh;
    acc.z = (acc.z + acc2.z) * izh;
    acc.w = (acc.w + acc2.w) * izh;

    float4 bb = *(const float4*)(b1 + lane * 4);
    float t0 = acc.x + bb.x, t1 = acc.y + bb.y, t2 = acc.z + bb.z, t3 = acc.w + bb.w;
    float4 o;
    o.x = (t0 > 0.f) ? t0 : expm1f(t0);
    o.y = (t1 > 0.f) ? t1 : expm1f(t1);
    o.z = (t2 > 0.f) ? t2 : expm1f(t2);
    o.w = (t3 > 0.f) ? t3 : expm1f(t3);
    *(float4*)(g_h1 + (size_t)n * HC + lane * 4) = o;
}

// ---------------- gemm2 + att2: h2pre = h1 @ W2, a_s2, a_d2 ----------------
__global__ void gemm2_kernel(const float* __restrict__ W2,
                             const float* __restrict__ as2w,
                             const float* __restrict__ ad2w, int nn) {
    __shared__ float sW[HC * NCLS];
    __shared__ float sas[NCLS], sad[NCLS];
    for (int i = threadIdx.x; i < HC * NCLS; i += 256) sW[i] = W2[i];
    if (threadIdx.x < NCLS) {
        sas[threadIdx.x] = as2w[threadIdx.x];
        sad[threadIdx.x] = ad2w[threadIdx.x];
    }
    __syncthreads();
    int warp = (blockIdx.x * 256 + threadIdx.x) >> 5;
    int lane = threadIdx.x & 31;
    if (warp >= nn) return;
    float4 v = *(const float4*)(g_h1 + (size_t)warp * HC + lane * 4);
    float p[NCLS];
    #pragma unroll
    for (int j = 0; j < NCLS; j++) {
        int c = lane * 4;
        p[j] = v.x * sW[(c + 0) * NCLS + j] + v.y * sW[(c + 1) * NCLS + j] +
               v.z * sW[(c + 2) * NCLS + j] + v.w * sW[(c + 3) * NCLS + j];
    }
    #pragma unroll
    for (int d = 16; d; d >>= 1) {
        #pragma unroll
        for (int j = 0; j < NCLS; j++) p[j] += __shfl_xor_sync(FULLMASK, p[j], d);
    }
    if (lane == 0) {
        float s = 0.f, dd = 0.f;
        #pragma unroll
        for (int j = 0; j < NCLS; j++) {
            g_h2pre[warp * 8 + j] = p[j];
            s += p[j] * sas[j];
            dd += p[j] * sad[j];
        }
        g_h2pre[warp * 8 + 7] = 0.f;
        g_as2[warp] = s;
        g_ad2[warp] = dd;
    }
}

// ---------------- agg2: softmax-aggregate layer 2 -> output ----------------
__global__ void agg2_kernel(const float* __restrict__ b2, float* __restrict__ out,
                            int nn) {
    int warp = (blockIdx.x * 256 + threadIdx.x) >> 5;
    int lane = threadIdx.x & 31;
    if (warp >= nn) return;
    int n = warp;
    int s0 = g_off[n], s1 = g_off[n + 1];
    float adn = g_ad2[n];

    float acc[8];
    #pragma unroll
    for (int j = 0; j < 8; j++) acc[j] = 0.f;
    float z = 0.f;
    for (int i = s0 + lane; i < s1; i += 32) {
        int s = g_csr[i];
        float t = g_as2[s] + adn;
        float e = fmaxf(t, 0.2f * t);
        float w = __expf(e);
        z += w;
        float4 v0 = *(const float4*)(g_h2pre + s * 8);
        float4 v1 = *(const float4*)(g_h2pre + s * 8 + 4);
        acc[0] += w * v0.x; acc[1] += w * v0.y;
        acc[2] += w * v0.z; acc[3] += w * v0.w;
        acc[4] += w * v1.x; acc[5] += w * v1.y;
        acc[6] += w * v1.z;
    }
    #pragma unroll
    for (int d = 16; d; d >>= 1) {
        z += __shfl_xor_sync(FULLMASK, z, d);
        #pragma unroll
        for (int j = 0; j < NCLS; j++) acc[j] += __shfl_xor_sync(FULLMASK, acc[j], d);
    }
    if (lane == 0) {
        float iz = 1.f / z;
        #pragma unroll
        for (int j = 0; j < NCLS; j++) out[n * NCLS + j] = acc[j] * iz + b2[j];
    }
}

// ---------------- launch ----------------
extern "C" void kernel_launch(void* const* d_in, const int* in_sizes, int n_in,
                              void* d_out, int out_size) {
    const float* x    = (const float*)d_in[0];
    const int*   ei   = (const int*)d_in[1];     // int32 (JAX x64 disabled)
    const float* W1   = (const float*)d_in[2];
    const float* as1w = (const float*)d_in[3];
    const float* ad1w = (const float*)d_in[4];
    const float* b1   = (const float*)d_in[5];
    const float* W2   = (const float*)d_in[6];
    const float* as2w = (const float*)d_in[7];
    const float* ad2w = (const float*)d_in[8];
    const float* b2   = (const float*)d_in[9];
    float* out = (float*)d_out;

    int nn = in_sizes[0] / F_IN;   // 50000
    int E  = in_sizes[1] / 2;      // 1600000
    int NB = (nn + 1023) / 1024;

    prep_w_kernel<<<(HC * KPAD + 255) / 256, 256>>>(W1);
    deg_init_kernel<<<(nn + 255) / 256, 256>>>(nn);
    deg_count_kernel<<<((E + 3) / 4 + 255) / 256, 256>>>(ei, E, nn);

    cudaFuncSetAttribute(gemm1_kernel, cudaFuncAttributeMaxDynamicSharedMemorySize,
                         GEMM1_SMEM);
    gemm1_kernel<<<(nn + 127) / 128, 256, GEMM1_SMEM>>>(x, as1w, ad1w, nn);

    scan1_kernel<<<NB, 1024>>>(nn);
    scan2_kernel<<<1, 64>>>(NB);
    scan3_kernel<<<(nn + 255) / 256, 256>>>(nn);
    scatter_kernel<<<(E + nn + 255) / 256, 256>>>(ei, E, nn);

    int wblocks = (nn * 32 + 255) / 256;
    agg1_kernel<<<wblocks, 256>>>(b1, nn);
    gemm2_kernel<<<wblocks, 256>>>(W2, as2w, ad2w, nn);
    agg2_kernel<<<wblocks, 256>>>(b2, out, nn);
}

// round 9
// speedup vs baseline: 1.9785x; 1.9785x over previous
#include <cuda_runtime.h>
#include <cuda_fp16.h>

#define FULLMASK 0xffffffffu

// ---------------- problem constants ----------------
#define F_IN   1433
#define HC     128          // HEADS*HID
#define NMAXN  50000
#define EMAXE  1600000
#define KPAD   1440         // 45 * 32
#define NCHUNK 45
#define NCLS   7

// ---------------- device scratch ----------------
__device__ float g_h1pre[NMAXN * HC];          // x @ W1
__device__ float g_h1[NMAXN * HC];             // elu(agg + b1)
__device__ float g_as1[NMAXN * 8];
__device__ float g_ad1[NMAXN * 8];
__device__ float g_h2pre[NMAXN * 8];           // h1 @ W2, padded stride 8
__device__ float g_as2[NMAXN];
__device__ float g_ad2[NMAXN];
__device__ int   g_deg[NMAXN];
__device__ int   g_off[NMAXN + 1];
__device__ int   g_cur[NMAXN];
__device__ int   g_csr[EMAXE + NMAXN];
__device__ int   g_bsum[64];
__device__ int   g_boff[64];
__device__ __half g_Wh[HC * KPAD];             // W1^T, [n][k], fp16

// ---------------- helpers ----------------
__device__ __forceinline__ void mma16816(float* c, const unsigned* a, const unsigned* b) {
    asm volatile(
        "mma.sync.aligned.m16n8k16.row.col.f32.f16.f16.f32 "
        "{%0,%1,%2,%3}, {%4,%5,%6,%7}, {%8,%9}, {%0,%1,%2,%3};"
        : "+f"(c[0]), "+f"(c[1]), "+f"(c[2]), "+f"(c[3])
        : "r"(a[0]), "r"(a[1]), "r"(a[2]), "r"(a[3]), "r"(b[0]), "r"(b[1]));
}

__device__ __forceinline__ unsigned smem_u32(const void* p) {
    unsigned a;
    asm("{ .reg .u64 t; cvta.to.shared.u64 t, %1; cvt.u32.u64 %0, t; }"
        : "=r"(a) : "l"(p));
    return a;
}

__device__ __forceinline__ void cp_async16(unsigned saddr, const void* gaddr) {
    asm volatile("cp.async.cg.shared.global [%0], [%1], 16;"
                 :: "r"(saddr), "l"(gaddr));
}
#define CP_COMMIT() asm volatile("cp.async.commit_group;" ::: "memory")
#define CP_WAIT0()  asm volatile("cp.async.wait_group 0;" ::: "memory")

__device__ __forceinline__ unsigned pack_h2(float lo, float hi) {
    __half2 h = __floats2half2_rn(lo, hi);
    return *reinterpret_cast<unsigned*>(&h);
}

// ---------------- prep: transpose W1 -> fp16 ----------------
__global__ void prep_w_kernel(const float* __restrict__ W1) {
    int idx = blockIdx.x * 256 + threadIdx.x;
    if (idx >= HC * KPAD) return;
    int n = idx / KPAD;
    int k = idx - n * KPAD;
    float v = (k < F_IN) ? W1[k * HC + n] : 0.f;
    g_Wh[idx] = __float2half_rn(v);
}

// ---------------- CSR build (edge_index is int32) ----------
__global__ void deg_init_kernel(int nn) {
    int t = blockIdx.x * 256 + threadIdx.x;
    if (t < nn) g_deg[t] = 1;  // self loop
}

__global__ void deg_count_kernel(const int* __restrict__ ei, int E, int nn) {
    int t = blockIdx.x * 256 + threadIdx.x;
    int base = t * 4;
    if (base + 3 < E) {
        int4 d = *(const int4*)(ei + E + base);
        if ((unsigned)d.x < (unsigned)nn) atomicAdd(&g_deg[d.x], 1);
        if ((unsigned)d.y < (unsigned)nn) atomicAdd(&g_deg[d.y], 1);
        if ((unsigned)d.z < (unsigned)nn) atomicAdd(&g_deg[d.z], 1);
        if ((unsigned)d.w < (unsigned)nn) atomicAdd(&g_deg[d.w], 1);
    } else {
        for (int i = base; i < E; i++) {
            int dst = ei[E + i];
            if ((unsigned)dst < (unsigned)nn) atomicAdd(&g_deg[dst], 1);
        }
    }
}

__global__ void scan1_kernel(int nn) {
    int b = blockIdx.x;
    int t = threadIdx.x;
    int idx = b * 1024 + t;
    int v = (idx < nn) ? g_deg[idx] : 0;
    int lane = t & 31, w = t >> 5;
    int s = v;
    #pragma unroll
    for (int d = 1; d < 32; d <<= 1) {
        int u = __shfl_up_sync(FULLMASK, s, d);
        if (lane >= d) s += u;
    }
    __shared__ int ws[32];
    if (lane == 31) ws[w] = s;
    __syncthreads();
    if (w == 0) {
        int x2 = ws[lane];
        #pragma unroll
        for (int d = 1; d < 32; d <<= 1) {
            int u = __shfl_up_sync(FULLMASK, x2, d);
            if (lane >= d) x2 += u;
        }
        ws[lane] = x2;
    }
    __syncthreads();
    int incl = s + ((w > 0) ? ws[w - 1] : 0);
    if (idx < nn) g_off[idx + 1] = incl;
    if (t == 1023) g_bsum[b] = incl;
}

__global__ void scan2_kernel(int nb) {
    int t = threadIdx.x;
    int v = (t < nb) ? g_bsum[t] : 0;
    int lane = t & 31, w = t >> 5;
    int s = v;
    #pragma unroll
    for (int d = 1; d < 32; d <<= 1) {
        int u = __shfl_up_sync(FULLMASK, s, d);
        if (lane >= d) s += u;
    }
    __shared__ int ws0;
    if (w == 0 && lane == 31) ws0 = s;
    __syncthreads();
    if (w == 1) s += ws0;
    if (t < 64) g_boff[t] = s - v;   // exclusive
}

__global__ void scan3_kernel(int nn) {
    int idx = blockIdx.x * 256 + threadIdx.x;
    if (idx >= nn) return;
    int add = g_boff[idx >> 10];
    int o = g_off[idx + 1] + add;
    g_off[idx + 1] = o;
    g_cur[idx] = o - g_deg[idx];
    if (idx == 0) g_off[0] = 0;
}

__global__ void scatter_kernel(const int* __restrict__ ei, int E, int nn) {
    int t = blockIdx.x * 256 + threadIdx.x;
    if (t < E) {
        int src = ei[t];
        int dst = ei[E + t];
        if ((unsigned)dst < (unsigned)nn && (unsigned)src < (unsigned)nn) {
            int pos = atomicAdd(&g_cur[dst], 1);
            g_csr[pos] = src;
        }
    } else if (t < E + nn) {
        int n = t - E;
        int pos = atomicAdd(&g_cur[n], 1);
        g_csr[pos] = n;
    }
}

// ---------------- GEMM1: h1pre = x @ W1 (fp16 HMMA, smem-staged A) ---------
// CTA tile 128x128, K-chunk 32. 8 warps, each 64x32 (warp grid 2Mx4N).
// smem rows 40 halves (80B), conflict-free. A/B fp16 single plane,
// 2 stages each: A[2] @ 0, B[2] @ 20480. Total 40960 B.
#define SROWH  40
#define PST    10240
#define GEMM1_SMEM 40960

__global__ void __launch_bounds__(256, 2) gemm1_kernel(
        const float* __restrict__ x,
        const float* __restrict__ att_s, const float* __restrict__ att_d,
        int n_rows) {
    extern __shared__ char smem[];
    unsigned sb = smem_u32(smem);

    int tid = threadIdx.x;
    int lane = tid & 31;
    int wid = tid >> 5;
    int m0 = blockIdx.x * 128;
    int mw = (wid & 1) * 64;
    int nw = (wid >> 1) * 32;
    int g = lane >> 2;
    int t4 = lane & 3;

    float acc[4][4][4];
    #pragma unroll
    for (int mi = 0; mi < 4; mi++)
        #pragma unroll
        for (int ni = 0; ni < 4; ni++)
            #pragma unroll
            for (int q = 0; q < 4; q++) acc[mi][ni][q] = 0.f;

    float xa[16];
    int rA = tid >> 4;              // row this thread converts (fixed)
    int c2A = (tid & 15) * 2;       // col pair base (fixed)
    int gmA = m0 + rA;
    bool rvA = gmA < n_rows;
    const float* xrow = x + (size_t)gmA * F_IN;

    auto loadA = [&](int ch) {
        int k0 = ch * 32;
        #pragma unroll
        for (int i = 0; i < 8; i++) {
            int gk = k0 + c2A;
            const float* xp = xrow + (size_t)i * 16 * F_IN + gk;
            bool rv = rvA && (gmA + i * 16 < n_rows);
            xa[2 * i]     = (rv && gk < F_IN)     ? __ldg(xp)     : 0.f;
            xa[2 * i + 1] = (rv && gk + 1 < F_IN) ? __ldg(xp + 1) : 0.f;
        }
    };
    auto convA = [&](int st) {
        char* dst = smem + st * PST;
        #pragma unroll
        for (int i = 0; i < 8; i++) {
            int r = rA + i * 16;
            unsigned hp = pack_h2(xa[2 * i], xa[2 * i + 1]);
            *(unsigned*)(dst + (unsigned)(r * 80 + c2A * 2)) = hp;
        }
    };
    auto loadB = [&](int st, int ch) {
        unsigned base = sb + 20480 + st * PST;
        int k0 = ch * 32;
        #pragma unroll
        for (int j = 0; j < 2; j++) {
            int s = tid + 256 * j;       // 0..511
            int r = s >> 2;
            int q = s & 3;
            cp_async16(base + (unsigned)(r * 80 + q * 16),
                       g_Wh + (size_t)r * KPAD + k0 + q * 8);
        }
        CP_COMMIT();
    };

    // prologue: A(0) converted into st0, xa <- A(1), B(0) in flight
    loadA(0);
    convA(0);
    loadB(0, 0);
    loadA(1);

    for (int ch = 0; ch < NCHUNK; ch++) {
        int st = ch & 1;
        CP_WAIT0();          // B(ch) landed (only group in flight)
        __syncthreads();     // all warps done with MMA(ch-1); stage st^1 free

        if (ch + 1 < NCHUNK) loadB(st ^ 1, ch + 1);   // overlaps MMA below

        const __half* pA = (const __half*)(smem + st * PST);
        const __half* pB = (const __half*)(smem + 20480 + st * PST);

        #pragma unroll
        for (int kk = 0; kk < 2; kk++) {
            int kc = kk * 16 + t4 * 2;
            unsigned bh[4][2];
            #pragma unroll
            for (int ni = 0; ni < 4; ni++) {
                int bn = nw + ni * 8 + g;
                bh[ni][0] = *(const unsigned*)&pB[bn * SROWH + kc];
                bh[ni][1] = *(const unsigned*)&pB[bn * SROWH + kc + 8];
            }
            #pragma unroll
            for (int mi = 0; mi < 4; mi++) {
                int ar = mw + mi * 16 + g;
                unsigned ah[4];
                ah[0] = *(const unsigned*)&pA[ar * SROWH + kc];
                ah[1] = *(const unsigned*)&pA[(ar + 8) * SROWH + kc];
                ah[2] = *(const unsigned*)&pA[ar * SROWH + kc + 8];
                ah[3] = *(const unsigned*)&pA[(ar + 8) * SROWH + kc + 8];
                #pragma unroll
                for (int ni = 0; ni < 4; ni++)
                    mma16816(acc[mi][ni], ah, bh[ni]);
            }
        }

        // convert next chunk's A into stage st^1 (overlaps other warps' MMA)
        if (ch + 1 < NCHUNK) {
            convA(st ^ 1);
            if (ch + 2 < NCHUNK) loadA(ch + 2);
        }
    }

    // ---- epilogue: store h1pre + fused att dots ----
    float2 asv[4], adv[4];
    #pragma unroll
    for (int ni = 0; ni < 4; ni++) {
        int c = nw + ni * 8 + t4 * 2;
        asv[ni] = *(const float2*)(att_s + c);
        adv[ni] = *(const float2*)(att_d + c);
    }
    int h0 = nw >> 4;

    #pragma unroll
    for (int mi = 0; mi < 4; mi++) {
        int row = m0 + mw + mi * 16 + g;
        #pragma unroll
        for (int ni = 0; ni < 4; ni++) {
            int col = nw + ni * 8 + t4 * 2;
            if (row < n_rows) {
                float2 v; v.x = acc[mi][ni][0]; v.y = acc[mi][ni][1];
                *(float2*)(g_h1pre + (size_t)row * HC + col) = v;
            }
            if (row + 8 < n_rows) {
                float2 v; v.x = acc[mi][ni][2]; v.y = acc[mi][ni][3];
                *(float2*)(g_h1pre + (size_t)(row + 8) * HC + col) = v;
            }
        }
        float psA[2] = {0.f, 0.f}, psB[2] = {0.f, 0.f};
        float pdA[2] = {0.f, 0.f}, pdB[2] = {0.f, 0.f};
        #pragma unroll
        for (int ni = 0; ni < 4; ni++) {
            int hh = ni >> 1;
            psA[hh] += acc[mi][ni][0] * asv[ni].x + acc[mi][ni][1] * asv[ni].y;
            psB[hh] += acc[mi][ni][2] * asv[ni].x + acc[mi][ni][3] * asv[ni].y;
            pdA[hh] += acc[mi][ni][0] * adv[ni].x + acc[mi][ni][1] * adv[ni].y;
            pdB[hh] += acc[mi][ni][2] * adv[ni].x + acc[mi][ni][3] * adv[ni].y;
        }
        #pragma unroll
        for (int hh = 0; hh < 2; hh++) {
            psA[hh] += __shfl_xor_sync(FULLMASK, psA[hh], 1);
            psA[hh] += __shfl_xor_sync(FULLMASK, psA[hh], 2);
            psB[hh] += __shfl_xor_sync(FULLMASK, psB[hh], 1);
            psB[hh] += __shfl_xor_sync(FULLMASK, psB[hh], 2);
            pdA[hh] += __shfl_xor_sync(FULLMASK, pdA[hh], 1);
            pdA[hh] += __shfl_xor_sync(FULLMASK, pdA[hh], 2);
            pdB[hh] += __shfl_xor_sync(FULLMASK, pdB[hh], 1);
            pdB[hh] += __shfl_xor_sync(FULLMASK, pdB[hh], 2);
        }
        if (t4 == 0) {
            if (row < n_rows) {
                g_as1[row * 8 + h0]     = psA[0];
                g_as1[row * 8 + h0 + 1] = psA[1];
                g_ad1[row * 8 + h0]     = pdA[0];
                g_ad1[row * 8 + h0 + 1] = pdA[1];
            }
            if (row + 8 < n_rows) {
                g_as1[(row + 8) * 8 + h0]     = psB[0];
                g_as1[(row + 8) * 8 + h0 + 1] = psB[1];
                g_ad1[(row + 8) * 8 + h0]     = pdB[0];
                g_ad1[(row + 8) * 8 + h0 + 1] = pdB[1];
            }
        }
    }
}

// ---------------- agg1: softmax-aggregate layer 1, + bias + ELU ----------------
__global__ void agg1_kernel(const float* __restrict__ b1, int nn) {
    int warp = (blockIdx.x * 256 + threadIdx.x) >> 5;
    int lane = threadIdx.x & 31;
    if (warp >= nn) return;
    int n = warp;
    int s0 = g_off[n], s1 = g_off[n + 1];

    float adv = (lane < 8) ? g_ad1[n * 8 + lane] : 0.f;
    float ad[8];
    #pragma unroll
    for (int h = 0; h < 8; h++) ad[h] = __shfl_sync(FULLMASK, adv, h);

    float z[8];
    #pragma unroll
    for (int h = 0; h < 8; h++) z[h] = 0.f;

    for (int i = s0 + lane; i < s1; i += 32) {
        int s = g_csr[i];
        float4 a0 = *(const float4*)(g_as1 + s * 8);
        float4 a1 = *(const float4*)(g_as1 + s * 8 + 4);
        float av[8] = {a0.x, a0.y, a0.z, a0.w, a1.x, a1.y, a1.z, a1.w};
        #pragma unroll
        for (int h = 0; h < 8; h++) {
            float t = av[h] + ad[h];
            float e = fmaxf(t, 0.2f * t);
            z[h] += __expf(e);
        }
    }
    #pragma unroll
    for (int d = 16; d; d >>= 1) {
        #pragma unroll
        for (int h = 0; h < 8; h++) z[h] += __shfl_xor_sync(FULLMASK, z[h], d);
    }
    int hme = lane >> 2;
    float izh = 1.f / z[hme];
    float adh = ad[hme];

    float4 acc = make_float4(0.f, 0.f, 0.f, 0.f);
    float4 acc2 = make_float4(0.f, 0.f, 0.f, 0.f);
    int i = s0;
    for (; i + 2 <= s1; i += 2) {
        int sA = g_csr[i], sB = g_csr[i + 1];
        float aA = __ldg(g_as1 + sA * 8 + hme);
        float aB = __ldg(g_as1 + sB * 8 + hme);
        float4 hA = *(const float4*)(g_h1pre + (size_t)sA * HC + lane * 4);
        float4 hB = *(const float4*)(g_h1pre + (size_t)sB * HC + lane * 4);
        float tA = aA + adh, tB = aB + adh;
        float eA = fmaxf(tA, 0.2f * tA), eB = fmaxf(tB, 0.2f * tB);
        float wA = __expf(eA), wB = __expf(eB);
        acc.x += wA * hA.x;  acc.y += wA * hA.y;
        acc.z += wA * hA.z;  acc.w += wA * hA.w;
        acc2.x += wB * hB.x; acc2.y += wB * hB.y;
        acc2.z += wB * hB.z; acc2.w += wB * hB.w;
    }
    if (i < s1) {
        int s = g_csr[i];
        float av = __ldg(g_as1 + s * 8 + hme);
        float tt = av + adh;
        float e = fmaxf(tt, 0.2f * tt);
        float w = __expf(e);
        float4 hv = *(const float4*)(g_h1pre + (size_t)s * HC + lane * 4);
        acc.x += w * hv.x; acc.y += w * hv.y;
        acc.z += w * hv.z; acc.w += w * hv.w;
    }
    acc.x = (acc.x + acc2.x) * izh;
    acc.y = (acc.y + acc2.y) * izh;
    acc.z = (acc.z + acc2.z) * izh;
    acc.w = (acc.w + acc2.w) * izh;

    float4 bb = *(const float4*)(b1 + lane * 4);
    float t0 = acc.x + bb.x, t1 = acc.y + bb.y, t2 = acc.z + bb.z, t3 = acc.w + bb.w;
    float4 o;
    o.x = (t0 > 0.f) ? t0 : expm1f(t0);
    o.y = (t1 > 0.f) ? t1 : expm1f(t1);
    o.z = (t2 > 0.f) ? t2 : expm1f(t2);
    o.w = (t3 > 0.f) ? t3 : expm1f(t3);
    *(float4*)(g_h1 + (size_t)n * HC + lane * 4) = o;
}

// ---------------- gemm2 + att2: h2pre = h1 @ W2, a_s2, a_d2 ----------------
__global__ void gemm2_kernel(const float* __restrict__ W2,
                             const float* __restrict__ as2w,
                             const float* __restrict__ ad2w, int nn) {
    __shared__ float sW[HC * NCLS];
    __shared__ float sas[NCLS], sad[NCLS];
    for (int i = threadIdx.x; i < HC * NCLS; i += 256) sW[i] = W2[i];
    if (threadIdx.x < NCLS) {
        sas[threadIdx.x] = as2w[threadIdx.x];
        sad[threadIdx.x] = ad2w[threadIdx.x];
    }
    __syncthreads();
    int warp = (blockIdx.x * 256 + threadIdx.x) >> 5;
    int lane = threadIdx.x & 31;
    if (warp >= nn) return;
    float4 v = *(const float4*)(g_h1 + (size_t)warp * HC + lane * 4);
    float p[NCLS];
    #pragma unroll
    for (int j = 0; j < NCLS; j++) {
        int c = lane * 4;
        p[j] = v.x * sW[(c + 0) * NCLS + j] + v.y * sW[(c + 1) * NCLS + j] +
               v.z * sW[(c + 2) * NCLS + j] + v.w * sW[(c + 3) * NCLS + j];
    }
    #pragma unroll
    for (int d = 16; d; d >>= 1) {
        #pragma unroll
        for (int j = 0; j < NCLS; j++) p[j] += __shfl_xor_sync(FULLMASK, p[j], d);
    }
    if (lane == 0) {
        float s = 0.f, dd = 0.f;
        #pragma unroll
        for (int j = 0; j < NCLS; j++) {
            g_h2pre[warp * 8 + j] = p[j];
            s += p[j] * sas[j];
            dd += p[j] * sad[j];
        }
        g_h2pre[warp * 8 + 7] = 0.f;
        g_as2[warp] = s;
        g_ad2[warp] = dd;
    }
}

// ---------------- agg2: softmax-aggregate layer 2 -> output ----------------
__global__ void agg2_kernel(const float* __restrict__ b2, float* __restrict__ out,
                            int nn) {
    int warp = (blockIdx.x * 256 + threadIdx.x) >> 5;
    int lane = threadIdx.x & 31;
    if (warp >= nn) return;
    int n = warp;
    int s0 = g_off[n], s1 = g_off[n + 1];
    float adn = g_ad2[n];

    float acc[8];
    #pragma unroll
    for (int j = 0; j < 8; j++) acc[j] = 0.f;
    float z = 0.f;
    for (int i = s0 + lane; i < s1; i += 32) {
        int s = g_csr[i];
        float t = g_as2[s] + adn;
        float e = fmaxf(t, 0.2f * t);
        float w = __expf(e);
        z += w;
        float4 v0 = *(const float4*)(g_h2pre + s * 8);
        float4 v1 = *(const float4*)(g_h2pre + s * 8 + 4);
        acc[0] += w * v0.x; acc[1] += w * v0.y;
        acc[2] += w * v0.z; acc[3] += w * v0.w;
        acc[4] += w * v1.x; acc[5] += w * v1.y;
        acc[6] += w * v1.z;
    }
    #pragma unroll
    for (int d = 16; d; d >>= 1) {
        z += __shfl_xor_sync(FULLMASK, z, d);
        #pragma unroll
        for (int j = 0; j < NCLS; j++) acc[j] += __shfl_xor_sync(FULLMASK, acc[j], d);
    }
    if (lane == 0) {
        float iz = 1.f / z;
        #pragma unroll
        for (int j = 0; j < NCLS; j++) out[n * NCLS + j] = acc[j] * iz + b2[j];
    }
}

// ---------------- launch ----------------
extern "C" void kernel_launch(void* const* d_in, const int* in_sizes, int n_in,
                              void* d_out, int out_size) {
    const float* x    = (const float*)d_in[0];
    const int*   ei   = (const int*)d_in[1];     // int32 (JAX x64 disabled)
    const float* W1   = (const float*)d_in[2];
    const float* as1w = (const float*)d_in[3];
    const float* ad1w = (const float*)d_in[4];
    const float* b1   = (const float*)d_in[5];
    const float* W2   = (const float*)d_in[6];
    const float* as2w = (const float*)d_in[7];
    const float* ad2w = (const float*)d_in[8];
    const float* b2   = (const float*)d_in[9];
    float* out = (float*)d_out;

    int nn = in_sizes[0] / F_IN;   // 50000
    int E  = in_sizes[1] / 2;      // 1600000
    int NB = (nn + 1023) / 1024;

    prep_w_kernel<<<(HC * KPAD + 255) / 256, 256>>>(W1);
    deg_init_kernel<<<(nn + 255) / 256, 256>>>(nn);
    deg_count_kernel<<<((E + 3) / 4 + 255) / 256, 256>>>(ei, E, nn);

    cudaFuncSetAttribute(gemm1_kernel, cudaFuncAttributeMaxDynamicSharedMemorySize,
                         GEMM1_SMEM);
    gemm1_kernel<<<(nn + 127) / 128, 256, GEMM1_SMEM>>>(x, as1w, ad1w, nn);

    scan1_kernel<<<NB, 1024>>>(nn);
    scan2_kernel<<<1, 64>>>(NB);
    scan3_kernel<<<(nn + 255) / 256, 256>>>(nn);
    scatter_kernel<<<(E + nn + 255) / 256, 256>>>(ei, E, nn);

    int wblocks = (nn * 32 + 255) / 256;
    agg1_kernel<<<wblocks, 256>>>(b1, nn);
    gemm2_kernel<<<wblocks, 256>>>(W2, as2w, ad2w, nn);
    agg2_kernel<<<wblocks, 256>>>(b2, out, nn);
}

// round 10
// speedup vs baseline: 2.2105x; 1.1173x over previous
#include <cuda_runtime.h>
#include <cuda_fp16.h>

#define FULLMASK 0xffffffffu

// ---------------- problem constants ----------------
#define F_IN   1433
#define HC     128          // HEADS*HID
#define NMAXN  50000
#define EMAXE  1600000
#define KPAD   1440         // 45 * 32
#define NCHUNK 45
#define NCLS   7

// ---------------- device scratch ----------------
__device__ __half g_h1preh[NMAXN * HC];        // x @ W1, fp16
__device__ float g_h1[NMAXN * HC];             // elu(agg + b1)
__device__ float g_as1[NMAXN * 8];
__device__ float g_ad1[NMAXN * 8];
__device__ float g_h2pre[NMAXN * 8];           // h1 @ W2, padded stride 8
__device__ float g_as2[NMAXN];
__device__ float g_ad2[NMAXN];
__device__ int   g_deg[NMAXN];
__device__ int   g_off[NMAXN + 1];
__device__ int   g_cur[NMAXN];
__device__ int   g_csr[EMAXE + NMAXN];
__device__ int   g_bsum[64];
__device__ int   g_boff[64];
__device__ __half g_Wh[HC * KPAD];             // W1^T, [n][k], fp16

// ---------------- helpers ----------------
__device__ __forceinline__ void mma16816(float* c, const unsigned* a, const unsigned* b) {
    asm volatile(
        "mma.sync.aligned.m16n8k16.row.col.f32.f16.f16.f32 "
        "{%0,%1,%2,%3}, {%4,%5,%6,%7}, {%8,%9}, {%0,%1,%2,%3};"
        : "+f"(c[0]), "+f"(c[1]), "+f"(c[2]), "+f"(c[3])
        : "r"(a[0]), "r"(a[1]), "r"(a[2]), "r"(a[3]), "r"(b[0]), "r"(b[1]));
}

__device__ __forceinline__ unsigned smem_u32(const void* p) {
    unsigned a;
    asm("{ .reg .u64 t; cvta.to.shared.u64 t, %1; cvt.u32.u64 %0, t; }"
        : "=r"(a) : "l"(p));
    return a;
}

__device__ __forceinline__ void cp_async16(unsigned saddr, const void* gaddr) {
    asm volatile("cp.async.cg.shared.global [%0], [%1], 16;"
                 :: "r"(saddr), "l"(gaddr));
}
#define CP_COMMIT() asm volatile("cp.async.commit_group;" ::: "memory")
#define CP_WAIT0()  asm volatile("cp.async.wait_group 0;" ::: "memory")

__device__ __forceinline__ unsigned pack_h2(float lo, float hi) {
    __half2 h = __floats2half2_rn(lo, hi);
    return *reinterpret_cast<unsigned*>(&h);
}

// ---------------- prep: transpose W1 -> fp16 ----------------
__global__ void prep_w_kernel(const float* __restrict__ W1) {
    int idx = blockIdx.x * 256 + threadIdx.x;
    if (idx >= HC * KPAD) return;
    int n = idx / KPAD;
    int k = idx - n * KPAD;
    float v = (k < F_IN) ? W1[k * HC + n] : 0.f;
    g_Wh[idx] = __float2half_rn(v);
}

// ---------------- CSR build (edge_index is int32) ----------
__global__ void deg_init_kernel(int nn) {
    int t = blockIdx.x * 256 + threadIdx.x;
    if (t < nn) g_deg[t] = 1;  // self loop
}

// 16 edges per thread via 4 int4 loads
__global__ void deg_count_kernel(const int* __restrict__ ei, int E, int nn) {
    int t = blockIdx.x * 256 + threadIdx.x;
    int base = t * 16;
    if (base + 15 < E) {
        #pragma unroll
        for (int j = 0; j < 4; j++) {
            int4 d = *(const int4*)(ei + E + base + j * 4);
            if ((unsigned)d.x < (unsigned)nn) atomicAdd(&g_deg[d.x], 1);
            if ((unsigned)d.y < (unsigned)nn) atomicAdd(&g_deg[d.y], 1);
            if ((unsigned)d.z < (unsigned)nn) atomicAdd(&g_deg[d.z], 1);
            if ((unsigned)d.w < (unsigned)nn) atomicAdd(&g_deg[d.w], 1);
        }
    } else {
        for (int i = base; i < E; i++) {
            int dst = ei[E + i];
            if ((unsigned)dst < (unsigned)nn) atomicAdd(&g_deg[dst], 1);
        }
    }
}

__global__ void scan1_kernel(int nn) {
    int b = blockIdx.x;
    int t = threadIdx.x;
    int idx = b * 1024 + t;
    int v = (idx < nn) ? g_deg[idx] : 0;
    int lane = t & 31, w = t >> 5;
    int s = v;
    #pragma unroll
    for (int d = 1; d < 32; d <<= 1) {
        int u = __shfl_up_sync(FULLMASK, s, d);
        if (lane >= d) s += u;
    }
    __shared__ int ws[32];
    if (lane == 31) ws[w] = s;
    __syncthreads();
    if (w == 0) {
        int x2 = ws[lane];
        #pragma unroll
        for (int d = 1; d < 32; d <<= 1) {
            int u = __shfl_up_sync(FULLMASK, x2, d);
            if (lane >= d) x2 += u;
        }
        ws[lane] = x2;
    }
    __syncthreads();
    int incl = s + ((w > 0) ? ws[w - 1] : 0);
    if (idx < nn) g_off[idx + 1] = incl;
    if (t == 1023) g_bsum[b] = incl;
}

__global__ void scan2_kernel(int nb) {
    int t = threadIdx.x;
    int v = (t < nb) ? g_bsum[t] : 0;
    int lane = t & 31, w = t >> 5;
    int s = v;
    #pragma unroll
    for (int d = 1; d < 32; d <<= 1) {
        int u = __shfl_up_sync(FULLMASK, s, d);
        if (lane >= d) s += u;
    }
    __shared__ int ws0;
    if (w == 0 && lane == 31) ws0 = s;
    __syncthreads();
    if (w == 1) s += ws0;
    if (t < 64) g_boff[t] = s - v;   // exclusive
}

__global__ void scan3_kernel(int nn) {
    int idx = blockIdx.x * 256 + threadIdx.x;
    if (idx >= nn) return;
    int add = g_boff[idx >> 10];
    int o = g_off[idx + 1] + add;
    g_off[idx + 1] = o;
    g_cur[idx] = o - g_deg[idx];
    if (idx == 0) g_off[0] = 0;
}

__global__ void scatter_kernel(const int* __restrict__ ei, int E, int nn) {
    int t = blockIdx.x * 256 + threadIdx.x;
    if (t < E) {
        int src = ei[t];
        int dst = ei[E + t];
        if ((unsigned)dst < (unsigned)nn && (unsigned)src < (unsigned)nn) {
            int pos = atomicAdd(&g_cur[dst], 1);
            g_csr[pos] = src;
        }
    } else if (t < E + nn) {
        int n = t - E;
        int pos = atomicAdd(&g_cur[n], 1);
        g_csr[pos] = n;
    }
}

// ---------------- GEMM1: h1pre = x @ W1 (fp16 HMMA, smem-staged A) ---------
// CTA tile 128x128, K-chunk 32. 8 warps, each 64x32 (warp grid 2Mx4N).
// smem rows 40 halves (80B), conflict-free. A/B fp16 single plane,
// 2 stages each: A[2] @ 0, B[2] @ 20480. Total 40960 B.
#define SROWH  40
#define PST    10240
#define GEMM1_SMEM 40960

__global__ void __launch_bounds__(256, 2) gemm1_kernel(
        const float* __restrict__ x,
        const float* __restrict__ att_s, const float* __restrict__ att_d,
        int n_rows) {
    extern __shared__ char smem[];
    unsigned sb = smem_u32(smem);

    int tid = threadIdx.x;
    int lane = tid & 31;
    int wid = tid >> 5;
    int m0 = blockIdx.x * 128;
    int mw = (wid & 1) * 64;
    int nw = (wid >> 1) * 32;
    int g = lane >> 2;
    int t4 = lane & 3;

    float acc[4][4][4];
    #pragma unroll
    for (int mi = 0; mi < 4; mi++)
        #pragma unroll
        for (int ni = 0; ni < 4; ni++)
            #pragma unroll
            for (int q = 0; q < 4; q++) acc[mi][ni][q] = 0.f;

    float xa[16];
    int rA = tid >> 4;              // row this thread converts (fixed)
    int c2A = (tid & 15) * 2;       // col pair base (fixed)
    int gmA = m0 + rA;
    bool rvA = gmA < n_rows;
    const float* xrow = x + (size_t)gmA * F_IN;

    auto loadA = [&](int ch) {
        int k0 = ch * 32;
        #pragma unroll
        for (int i = 0; i < 8; i++) {
            int gk = k0 + c2A;
            const float* xp = xrow + (size_t)i * 16 * F_IN + gk;
            bool rv = rvA && (gmA + i * 16 < n_rows);
            xa[2 * i]     = (rv && gk < F_IN)     ? __ldg(xp)     : 0.f;
            xa[2 * i + 1] = (rv && gk + 1 < F_IN) ? __ldg(xp + 1) : 0.f;
        }
    };
    auto convA = [&](int st) {
        char* dst = smem + st * PST;
        #pragma unroll
        for (int i = 0; i < 8; i++) {
            int r = rA + i * 16;
            unsigned hp = pack_h2(xa[2 * i], xa[2 * i + 1]);
            *(unsigned*)(dst + (unsigned)(r * 80 + c2A * 2)) = hp;
        }
    };
    auto loadB = [&](int st, int ch) {
        unsigned base = sb + 20480 + st * PST;
        int k0 = ch * 32;
        #pragma unroll
        for (int j = 0; j < 2; j++) {
            int s = tid + 256 * j;       // 0..511
            int r = s >> 2;
            int q = s & 3;
            cp_async16(base + (unsigned)(r * 80 + q * 16),
                       g_Wh + (size_t)r * KPAD + k0 + q * 8);
        }
        CP_COMMIT();
    };

    // prologue
    loadA(0);
    convA(0);
    loadB(0, 0);
    loadA(1);

    for (int ch = 0; ch < NCHUNK; ch++) {
        int st = ch & 1;
        CP_WAIT0();
        __syncthreads();

        if (ch + 1 < NCHUNK) loadB(st ^ 1, ch + 1);

        const __half* pA = (const __half*)(smem + st * PST);
        const __half* pB = (const __half*)(smem + 20480 + st * PST);

        #pragma unroll
        for (int kk = 0; kk < 2; kk++) {
            int kc = kk * 16 + t4 * 2;
            unsigned bh[4][2];
            #pragma unroll
            for (int ni = 0; ni < 4; ni++) {
                int bn = nw + ni * 8 + g;
                bh[ni][0] = *(const unsigned*)&pB[bn * SROWH + kc];
                bh[ni][1] = *(const unsigned*)&pB[bn * SROWH + kc + 8];
            }
            #pragma unroll
            for (int mi = 0; mi < 4; mi++) {
                int ar = mw + mi * 16 + g;
                unsigned ah[4];
                ah[0] = *(const unsigned*)&pA[ar * SROWH + kc];
                ah[1] = *(const unsigned*)&pA[(ar + 8) * SROWH + kc];
                ah[2] = *(const unsigned*)&pA[ar * SROWH + kc + 8];
                ah[3] = *(const unsigned*)&pA[(ar + 8) * SROWH + kc + 8];
                #pragma unroll
                for (int ni = 0; ni < 4; ni++)
                    mma16816(acc[mi][ni], ah, bh[ni]);
            }
        }

        if (ch + 1 < NCHUNK) {
            convA(st ^ 1);
            if (ch + 2 < NCHUNK) loadA(ch + 2);
        }
    }

    // ---- epilogue: store h1pre (fp16) + fused att dots ----
    float2 asv[4], adv[4];
    #pragma unroll
    for (int ni = 0; ni < 4; ni++) {
        int c = nw + ni * 8 + t4 * 2;
        asv[ni] = *(const float2*)(att_s + c);
        adv[ni] = *(const float2*)(att_d + c);
    }
    int h0 = nw >> 4;

    #pragma unroll
    for (int mi = 0; mi < 4; mi++) {
        int row = m0 + mw + mi * 16 + g;
        #pragma unroll
        for (int ni = 0; ni < 4; ni++) {
            int col = nw + ni * 8 + t4 * 2;
            if (row < n_rows) {
                unsigned hp = pack_h2(acc[mi][ni][0], acc[mi][ni][1]);
                *(unsigned*)(g_h1preh + (size_t)row * HC + col) = hp;
            }
            if (row + 8 < n_rows) {
                unsigned hp = pack_h2(acc[mi][ni][2], acc[mi][ni][3]);
                *(unsigned*)(g_h1preh + (size_t)(row + 8) * HC + col) = hp;
            }
        }
        float psA[2] = {0.f, 0.f}, psB[2] = {0.f, 0.f};
        float pdA[2] = {0.f, 0.f}, pdB[2] = {0.f, 0.f};
        #pragma unroll
        for (int ni = 0; ni < 4; ni++) {
            int hh = ni >> 1;
            psA[hh] += acc[mi][ni][0] * asv[ni].x + acc[mi][ni][1] * asv[ni].y;
            psB[hh] += acc[mi][ni][2] * asv[ni].x + acc[mi][ni][3] * asv[ni].y;
            pdA[hh] += acc[mi][ni][0] * adv[ni].x + acc[mi][ni][1] * adv[ni].y;
            pdB[hh] += acc[mi][ni][2] * adv[ni].x + acc[mi][ni][3] * adv[ni].y;
        }
        #pragma unroll
        for (int hh = 0; hh < 2; hh++) {
            psA[hh] += __shfl_xor_sync(FULLMASK, psA[hh], 1);
            psA[hh] += __shfl_xor_sync(FULLMASK, psA[hh], 2);
            psB[hh] += __shfl_xor_sync(FULLMASK, psB[hh], 1);
            psB[hh] += __shfl_xor_sync(FULLMASK, psB[hh], 2);
            pdA[hh] += __shfl_xor_sync(FULLMASK, pdA[hh], 1);
            pdA[hh] += __shfl_xor_sync(FULLMASK, pdA[hh], 2);
            pdB[hh] += __shfl_xor_sync(FULLMASK, pdB[hh], 1);
            pdB[hh] += __shfl_xor_sync(FULLMASK, pdB[hh], 2);
        }
        if (t4 == 0) {
            if (row < n_rows) {
                g_as1[row * 8 + h0]     = psA[0];
                g_as1[row * 8 + h0 + 1] = psA[1];
                g_ad1[row * 8 + h0]     = pdA[0];
                g_ad1[row * 8 + h0 + 1] = pdA[1];
            }
            if (row + 8 < n_rows) {
                g_as1[(row + 8) * 8 + h0]     = psB[0];
                g_as1[(row + 8) * 8 + h0 + 1] = psB[1];
                g_ad1[(row + 8) * 8 + h0]     = pdB[0];
                g_ad1[(row + 8) * 8 + h0 + 1] = pdB[1];
            }
        }
    }
}

// ---------------- agg1: single-pass softmax-aggregate, + bias + ELU --------
// Each warp = one node; all lanes walk all edges. Lane covers 4 dims of head
// (lane>>2). Unnormalized accumulation + z, normalize at end (scores bounded).
__global__ void agg1_kernel(const float* __restrict__ b1, int nn) {
    int warp = (blockIdx.x * 256 + threadIdx.x) >> 5;
    int lane = threadIdx.x & 31;
    if (warp >= nn) return;
    int n = warp;
    int s0 = g_off[n], s1 = g_off[n + 1];
    int hme = lane >> 2;
    float adh = __ldg(g_ad1 + n * 8 + hme);

    float4 acc = make_float4(0.f, 0.f, 0.f, 0.f);
    float4 acc2 = make_float4(0.f, 0.f, 0.f, 0.f);
    float z = 0.f, z2 = 0.f;
    int i = s0;
    for (; i + 2 <= s1; i += 2) {
        int sA = g_csr[i], sB = g_csr[i + 1];
        float aA = __ldg(g_as1 + sA * 8 + hme);
        float aB = __ldg(g_as1 + sB * 8 + hme);
        uint2 hA = *(const uint2*)(g_h1preh + (size_t)sA * HC + lane * 4);
        uint2 hB = *(const uint2*)(g_h1preh + (size_t)sB * HC + lane * 4);
        float tA = aA + adh, tB = aB + adh;
        float wA = __expf(fmaxf(tA, 0.2f * tA));
        float wB = __expf(fmaxf(tB, 0.2f * tB));
        z += wA; z2 += wB;
        float2 a01 = __half22float2(*(__half2*)&hA.x);
        float2 a23 = __half22float2(*(__half2*)&hA.y);
        float2 b01 = __half22float2(*(__half2*)&hB.x);
        float2 b23 = __half22float2(*(__half2*)&hB.y);
        acc.x += wA * a01.x;  acc.y += wA * a01.y;
        acc.z += wA * a23.x;  acc.w += wA * a23.y;
        acc2.x += wB * b01.x; acc2.y += wB * b01.y;
        acc2.z += wB * b23.x; acc2.w += wB * b23.y;
    }
    if (i < s1) {
        int s = g_csr[i];
        float av = __ldg(g_as1 + s * 8 + hme);
        uint2 hv = *(const uint2*)(g_h1preh + (size_t)s * HC + lane * 4);
        float tt = av + adh;
        float w = __expf(fmaxf(tt, 0.2f * tt));
        z += w;
        float2 a01 = __half22float2(*(__half2*)&hv.x);
        float2 a23 = __half22float2(*(__half2*)&hv.y);
        acc.x += w * a01.x; acc.y += w * a01.y;
        acc.z += w * a23.x; acc.w += w * a23.y;
    }
    float izh = 1.f / (z + z2);
    acc.x = (acc.x + acc2.x) * izh;
    acc.y = (acc.y + acc2.y) * izh;
    acc.z = (acc.z + acc2.z) * izh;
    acc.w = (acc.w + acc2.w) * izh;

    float4 bb = *(const float4*)(b1 + lane * 4);
    float t0 = acc.x + bb.x, t1 = acc.y + bb.y, t2 = acc.z + bb.z, t3 = acc.w + bb.w;
    float4 o;
    o.x = (t0 > 0.f) ? t0 : expm1f(t0);
    o.y = (t1 > 0.f) ? t1 : expm1f(t1);
    o.z = (t2 > 0.f) ? t2 : expm1f(t2);
    o.w = (t3 > 0.f) ? t3 : expm1f(t3);
    *(float4*)(g_h1 + (size_t)n * HC + lane * 4) = o;
}

// ---------------- gemm2 + att2: h2pre = h1 @ W2, a_s2, a_d2 ----------------
__global__ void gemm2_kernel(const float* __restrict__ W2,
                             const float* __restrict__ as2w,
                             const float* __restrict__ ad2w, int nn) {
    __shared__ float sW[HC * NCLS];
    __shared__ float sas[NCLS], sad[NCLS];
    for (int i = threadIdx.x; i < HC * NCLS; i += 256) sW[i] = W2[i];
    if (threadIdx.x < NCLS) {
        sas[threadIdx.x] = as2w[threadIdx.x];
        sad[threadIdx.x] = ad2w[threadIdx.x];
    }
    __syncthreads();
    int warp = (blockIdx.x * 256 + threadIdx.x) >> 5;
    int lane = threadIdx.x & 31;
    if (warp >= nn) return;
    float4 v = *(const float4*)(g_h1 + (size_t)warp * HC + lane * 4);
    float p[NCLS];
    #pragma unroll
    for (int j = 0; j < NCLS; j++) {
        int c = lane * 4;
        p[j] = v.x * sW[(c + 0) * NCLS + j] + v.y * sW[(c + 1) * NCLS + j] +
               v.z * sW[(c + 2) * NCLS + j] + v.w * sW[(c + 3) * NCLS + j];
    }
    #pragma unroll
    for (int d = 16; d; d >>= 1) {
        #pragma unroll
        for (int j = 0; j < NCLS; j++) p[j] += __shfl_xor_sync(FULLMASK, p[j], d);
    }
    if (lane == 0) {
        float s = 0.f, dd = 0.f;
        #pragma unroll
        for (int j = 0; j < NCLS; j++) {
            g_h2pre[warp * 8 + j] = p[j];
            s += p[j] * sas[j];
            dd += p[j] * sad[j];
        }
        g_h2pre[warp * 8 + 7] = 0.f;
        g_as2[warp] = s;
        g_ad2[warp] = dd;
    }
}

// ---------------- agg2: softmax-aggregate layer 2 -> output ----------------
__global__ void agg2_kernel(const float* __restrict__ b2, float* __restrict__ out,
                            int nn) {
    int warp = (blockIdx.x * 256 + threadIdx.x) >> 5;
    int lane = threadIdx.x & 31;
    if (warp >= nn) return;
    int n = warp;
    int s0 = g_off[n], s1 = g_off[n + 1];
    float adn = g_ad2[n];

    float acc[8];
    #pragma unroll
    for (int j = 0; j < 8; j++) acc[j] = 0.f;
    float z = 0.f;
    for (int i = s0 + lane; i < s1; i += 32) {
        int s = g_csr[i];
        float t = g_as2[s] + adn;
        float e = fmaxf(t, 0.2f * t);
        float w = __expf(e);
        z += w;
        float4 v0 = *(const float4*)(g_h2pre + s * 8);
        float4 v1 = *(const float4*)(g_h2pre + s * 8 + 4);
        acc[0] += w * v0.x; acc[1] += w * v0.y;
        acc[2] += w * v0.z; acc[3] += w * v0.w;
        acc[4] += w * v1.x; acc[5] += w * v1.y;
        acc[6] += w * v1.z;
    }
    #pragma unroll
    for (int d = 16; d; d >>= 1) {
        z += __shfl_xor_sync(FULLMASK, z, d);
        #pragma unroll
        for (int j = 0; j < NCLS; j++) acc[j] += __shfl_xor_sync(FULLMASK, acc[j], d);
    }
    if (lane == 0) {
        float iz = 1.f / z;
        #pragma unroll
        for (int j = 0; j < NCLS; j++) out[n * NCLS + j] = acc[j] * iz + b2[j];
    }
}

// ---------------- launch ----------------
extern "C" void kernel_launch(void* const* d_in, const int* in_sizes, int n_in,
                              void* d_out, int out_size) {
    const float* x    = (const float*)d_in[0];
    const int*   ei   = (const int*)d_in[1];     // int32 (JAX x64 disabled)
    const float* W1   = (const float*)d_in[2];
    const float* as1w = (const float*)d_in[3];
    const float* ad1w = (const float*)d_in[4];
    const float* b1   = (const float*)d_in[5];
    const float* W2   = (const float*)d_in[6];
    const float* as2w = (const float*)d_in[7];
    const float* ad2w = (const float*)d_in[8];
    const float* b2   = (const float*)d_in[9];
    float* out = (float*)d_out;

    int nn = in_sizes[0] / F_IN;   // 50000
    int E  = in_sizes[1] / 2;      // 1600000
    int NB = (nn + 1023) / 1024;

    prep_w_kernel<<<(HC * KPAD + 255) / 256, 256>>>(W1);
    deg_init_kernel<<<(nn + 255) / 256, 256>>>(nn);
    deg_count_kernel<<<((E + 15) / 16 + 255) / 256, 256>>>(ei, E, nn);

    cudaFuncSetAttribute(gemm1_kernel, cudaFuncAttributeMaxDynamicSharedMemorySize,
                         GEMM1_SMEM);
    gemm1_kernel<<<(nn + 127) / 128, 256, GEMM1_SMEM>>>(x, as1w, ad1w, nn);

    scan1_kernel<<<NB, 1024>>>(nn);
    scan2_kernel<<<1, 64>>>(NB);
    scan3_kernel<<<(nn + 255) / 256, 256>>>(nn);
    scatter_kernel<<<(E + nn + 255) / 256, 256>>>(ei, E, nn);

    int wblocks = (nn * 32 + 255) / 256;
    agg1_kernel<<<wblocks, 256>>>(b1, nn);
    gemm2_kernel<<<wblocks, 256>>>(W2, as2w, ad2w, nn);
    agg2_kernel<<<wblocks, 256>>>(b2, out, nn);
}

// round 11
// speedup vs baseline: 2.3575x; 1.0665x over previous
#include <cuda_runtime.h>
#include <cuda_fp16.h>

#define FULLMASK 0xffffffffu

// ---------------- problem constants ----------------
#define F_IN   1433
#define HC     128          // HEADS*HID
#define NMAXN  50000
#define EMAXE  1600000
#define KPAD   1440         // 45 * 32
#define NCHUNK 45
#define NCLS   7

// ---------------- device scratch ----------------
__device__ __half g_h1preh[NMAXN * HC];        // x @ W1, fp16
__device__ float g_h1[NMAXN * HC];             // elu(agg + b1)
__device__ float g_as1[NMAXN * 8];
__device__ float g_ad1[NMAXN * 8];
__device__ float g_h2pre[NMAXN * 8];           // h1 @ W2, padded stride 8
__device__ float g_as2[NMAXN];
__device__ float g_ad2[NMAXN];
__device__ int   g_deg[NMAXN];
__device__ int   g_off[NMAXN + 1];
__device__ int   g_cur[NMAXN];
__device__ int   g_csr[EMAXE + NMAXN];
__device__ int   g_bsum[64];
__device__ int   g_boff[64];
__device__ __half g_Wh[HC * KPAD];             // W1^T, [n][k], fp16

// ---------------- helpers ----------------
__device__ __forceinline__ void mma16816(float* c, const unsigned* a, const unsigned* b) {
    asm volatile(
        "mma.sync.aligned.m16n8k16.row.col.f32.f16.f16.f32 "
        "{%0,%1,%2,%3}, {%4,%5,%6,%7}, {%8,%9}, {%0,%1,%2,%3};"
        : "+f"(c[0]), "+f"(c[1]), "+f"(c[2]), "+f"(c[3])
        : "r"(a[0]), "r"(a[1]), "r"(a[2]), "r"(a[3]), "r"(b[0]), "r"(b[1]));
}

__device__ __forceinline__ unsigned smem_u32(const void* p) {
    unsigned a;
    asm("{ .reg .u64 t; cvta.to.shared.u64 t, %1; cvt.u32.u64 %0, t; }"
        : "=r"(a) : "l"(p));
    return a;
}

__device__ __forceinline__ void cp_async16(unsigned saddr, const void* gaddr) {
    asm volatile("cp.async.cg.shared.global [%0], [%1], 16;"
                 :: "r"(saddr), "l"(gaddr));
}
#define CP_COMMIT() asm volatile("cp.async.commit_group;" ::: "memory")
#define CP_WAIT0()  asm volatile("cp.async.wait_group 0;" ::: "memory")

__device__ __forceinline__ unsigned pack_h2(float lo, float hi) {
    __half2 h = __floats2half2_rn(lo, hi);
    return *reinterpret_cast<unsigned*>(&h);
}

// ---------------- prep: transpose W1 -> fp16 ----------------
__global__ void prep_w_kernel(const float* __restrict__ W1) {
    int idx = blockIdx.x * 256 + threadIdx.x;
    if (idx >= HC * KPAD) return;
    int n = idx / KPAD;
    int k = idx - n * KPAD;
    float v = (k < F_IN) ? W1[k * HC + n] : 0.f;
    g_Wh[idx] = __float2half_rn(v);
}

// ---------------- CSR build (edge_index is int32) ----------
__global__ void deg_init_kernel(int nn) {
    int t = blockIdx.x * 256 + threadIdx.x;
    if (t < nn) g_deg[t] = 1;  // self loop
}

// 16 edges per thread via 4 int4 loads
__global__ void deg_count_kernel(const int* __restrict__ ei, int E, int nn) {
    int t = blockIdx.x * 256 + threadIdx.x;
    int base = t * 16;
    if (base + 15 < E) {
        #pragma unroll
        for (int j = 0; j < 4; j++) {
            int4 d = *(const int4*)(ei + E + base + j * 4);
            if ((unsigned)d.x < (unsigned)nn) atomicAdd(&g_deg[d.x], 1);
            if ((unsigned)d.y < (unsigned)nn) atomicAdd(&g_deg[d.y], 1);
            if ((unsigned)d.z < (unsigned)nn) atomicAdd(&g_deg[d.z], 1);
            if ((unsigned)d.w < (unsigned)nn) atomicAdd(&g_deg[d.w], 1);
        }
    } else {
        for (int i = base; i < E; i++) {
            int dst = ei[E + i];
            if ((unsigned)dst < (unsigned)nn) atomicAdd(&g_deg[dst], 1);
        }
    }
}

__global__ void scan1_kernel(int nn) {
    int b = blockIdx.x;
    int t = threadIdx.x;
    int idx = b * 1024 + t;
    int v = (idx < nn) ? g_deg[idx] : 0;
    int lane = t & 31, w = t >> 5;
    int s = v;
    #pragma unroll
    for (int d = 1; d < 32; d <<= 1) {
        int u = __shfl_up_sync(FULLMASK, s, d);
        if (lane >= d) s += u;
    }
    __shared__ int ws[32];
    if (lane == 31) ws[w] = s;
    __syncthreads();
    if (w == 0) {
        int x2 = ws[lane];
        #pragma unroll
        for (int d = 1; d < 32; d <<= 1) {
            int u = __shfl_up_sync(FULLMASK, x2, d);
            if (lane >= d) x2 += u;
        }
        ws[lane] = x2;
    }
    __syncthreads();
    int incl = s + ((w > 0) ? ws[w - 1] : 0);
    if (idx < nn) g_off[idx + 1] = incl;
    if (t == 1023) g_bsum[b] = incl;
}

__global__ void scan2_kernel(int nb) {
    int t = threadIdx.x;
    int v = (t < nb) ? g_bsum[t] : 0;
    int lane = t & 31, w = t >> 5;
    int s = v;
    #pragma unroll
    for (int d = 1; d < 32; d <<= 1) {
        int u = __shfl_up_sync(FULLMASK, s, d);
        if (lane >= d) s += u;
    }
    __shared__ int ws0;
    if (w == 0 && lane == 31) ws0 = s;
    __syncthreads();
    if (w == 1) s += ws0;
    if (t < 64) g_boff[t] = s - v;   // exclusive
}

__global__ void scan3_kernel(int nn) {
    int idx = blockIdx.x * 256 + threadIdx.x;
    if (idx >= nn) return;
    int add = g_boff[idx >> 10];
    int o = g_off[idx + 1] + add;
    g_off[idx + 1] = o;
    g_cur[idx] = o - g_deg[idx];
    if (idx == 0) g_off[0] = 0;
}

__global__ void scatter_kernel(const int* __restrict__ ei, int E, int nn) {
    int t = blockIdx.x * 256 + threadIdx.x;
    if (t < E) {
        int src = ei[t];
        int dst = ei[E + t];
        if ((unsigned)dst < (unsigned)nn && (unsigned)src < (unsigned)nn) {
            int pos = atomicAdd(&g_cur[dst], 1);
            g_csr[pos] = src;
        }
    } else if (t < E + nn) {
        int n = t - E;
        int pos = atomicAdd(&g_cur[n], 1);
        g_csr[pos] = n;
    }
}

// ---------------- GEMM1: h1pre = x @ W1 (fp16 HMMA, smem-staged A) ---------
#define SROWH  40
#define PST    10240
#define GEMM1_SMEM 40960

__global__ void __launch_bounds__(256, 2) gemm1_kernel(
        const float* __restrict__ x,
        const float* __restrict__ att_s, const float* __restrict__ att_d,
        int n_rows) {
    extern __shared__ char smem[];
    unsigned sb = smem_u32(smem);

    int tid = threadIdx.x;
    int lane = tid & 31;
    int wid = tid >> 5;
    int m0 = blockIdx.x * 128;
    int mw = (wid & 1) * 64;
    int nw = (wid >> 1) * 32;
    int g = lane >> 2;
    int t4 = lane & 3;

    float acc[4][4][4];
    #pragma unroll
    for (int mi = 0; mi < 4; mi++)
        #pragma unroll
        for (int ni = 0; ni < 4; ni++)
            #pragma unroll
            for (int q = 0; q < 4; q++) acc[mi][ni][q] = 0.f;

    float xa[16];
    int rA = tid >> 4;
    int c2A = (tid & 15) * 2;
    int gmA = m0 + rA;
    bool rvA = gmA < n_rows;
    const float* xrow = x + (size_t)gmA * F_IN;

    auto loadA = [&](int ch) {
        int k0 = ch * 32;
        #pragma unroll
        for (int i = 0; i < 8; i++) {
            int gk = k0 + c2A;
            const float* xp = xrow + (size_t)i * 16 * F_IN + gk;
            bool rv = rvA && (gmA + i * 16 < n_rows);
            xa[2 * i]     = (rv && gk < F_IN)     ? __ldg(xp)     : 0.f;
            xa[2 * i + 1] = (rv && gk + 1 < F_IN) ? __ldg(xp + 1) : 0.f;
        }
    };
    auto convA = [&](int st) {
        char* dst = smem + st * PST;
        #pragma unroll
        for (int i = 0; i < 8; i++) {
            int r = rA + i * 16;
            unsigned hp = pack_h2(xa[2 * i], xa[2 * i + 1]);
            *(unsigned*)(dst + (unsigned)(r * 80 + c2A * 2)) = hp;
        }
    };
    auto loadB = [&](int st, int ch) {
        unsigned base = sb + 20480 + st * PST;
        int k0 = ch * 32;
        #pragma unroll
        for (int j = 0; j < 2; j++) {
            int s = tid + 256 * j;
            int r = s >> 2;
            int q = s & 3;
            cp_async16(base + (unsigned)(r * 80 + q * 16),
                       g_Wh + (size_t)r * KPAD + k0 + q * 8);
        }
        CP_COMMIT();
    };

    loadA(0);
    convA(0);
    loadB(0, 0);
    loadA(1);

    for (int ch = 0; ch < NCHUNK; ch++) {
        int st = ch & 1;
        CP_WAIT0();
        __syncthreads();

        if (ch + 1 < NCHUNK) loadB(st ^ 1, ch + 1);

        const __half* pA = (const __half*)(smem + st * PST);
        const __half* pB = (const __half*)(smem + 20480 + st * PST);

        #pragma unroll
        for (int kk = 0; kk < 2; kk++) {
            int kc = kk * 16 + t4 * 2;
            unsigned bh[4][2];
            #pragma unroll
            for (int ni = 0; ni < 4; ni++) {
                int bn = nw + ni * 8 + g;
                bh[ni][0] = *(const unsigned*)&pB[bn * SROWH + kc];
                bh[ni][1] = *(const unsigned*)&pB[bn * SROWH + kc + 8];
            }
            #pragma unroll
            for (int mi = 0; mi < 4; mi++) {
                int ar = mw + mi * 16 + g;
                unsigned ah[4];
                ah[0] = *(const unsigned*)&pA[ar * SROWH + kc];
                ah[1] = *(const unsigned*)&pA[(ar + 8) * SROWH + kc];
                ah[2] = *(const unsigned*)&pA[ar * SROWH + kc + 8];
                ah[3] = *(const unsigned*)&pA[(ar + 8) * SROWH + kc + 8];
                #pragma unroll
                for (int ni = 0; ni < 4; ni++)
                    mma16816(acc[mi][ni], ah, bh[ni]);
            }
        }

        if (ch + 1 < NCHUNK) {
            convA(st ^ 1);
            if (ch + 2 < NCHUNK) loadA(ch + 2);
        }
    }

    // ---- epilogue: store h1pre (fp16) + fused att dots ----
    float2 asv[4], adv[4];
    #pragma unroll
    for (int ni = 0; ni < 4; ni++) {
        int c = nw + ni * 8 + t4 * 2;
        asv[ni] = *(const float2*)(att_s + c);
        adv[ni] = *(const float2*)(att_d + c);
    }
    int h0 = nw >> 4;

    #pragma unroll
    for (int mi = 0; mi < 4; mi++) {
        int row = m0 + mw + mi * 16 + g;
        #pragma unroll
        for (int ni = 0; ni < 4; ni++) {
            int col = nw + ni * 8 + t4 * 2;
            if (row < n_rows) {
                unsigned hp = pack_h2(acc[mi][ni][0], acc[mi][ni][1]);
                *(unsigned*)(g_h1preh + (size_t)row * HC + col) = hp;
            }
            if (row + 8 < n_rows) {
                unsigned hp = pack_h2(acc[mi][ni][2], acc[mi][ni][3]);
                *(unsigned*)(g_h1preh + (size_t)(row + 8) * HC + col) = hp;
            }
        }
        float psA[2] = {0.f, 0.f}, psB[2] = {0.f, 0.f};
        float pdA[2] = {0.f, 0.f}, pdB[2] = {0.f, 0.f};
        #pragma unroll
        for (int ni = 0; ni < 4; ni++) {
            int hh = ni >> 1;
            psA[hh] += acc[mi][ni][0] * asv[ni].x + acc[mi][ni][1] * asv[ni].y;
            psB[hh] += acc[mi][ni][2] * asv[ni].x + acc[mi][ni][3] * asv[ni].y;
            pdA[hh] += acc[mi][ni][0] * adv[ni].x + acc[mi][ni][1] * adv[ni].y;
            pdB[hh] += acc[mi][ni][2] * adv[ni].x + acc[mi][ni][3] * adv[ni].y;
        }
        #pragma unroll
        for (int hh = 0; hh < 2; hh++) {
            psA[hh] += __shfl_xor_sync(FULLMASK, psA[hh], 1);
            psA[hh] += __shfl_xor_sync(FULLMASK, psA[hh], 2);
            psB[hh] += __shfl_xor_sync(FULLMASK, psB[hh], 1);
            psB[hh] += __shfl_xor_sync(FULLMASK, psB[hh], 2);
            pdA[hh] += __shfl_xor_sync(FULLMASK, pdA[hh], 1);
            pdA[hh] += __shfl_xor_sync(FULLMASK, pdA[hh], 2);
            pdB[hh] += __shfl_xor_sync(FULLMASK, pdB[hh], 1);
            pdB[hh] += __shfl_xor_sync(FULLMASK, pdB[hh], 2);
        }
        if (t4 == 0) {
            if (row < n_rows) {
                g_as1[row * 8 + h0]     = psA[0];
                g_as1[row * 8 + h0 + 1] = psA[1];
                g_ad1[row * 8 + h0]     = pdA[0];
                g_ad1[row * 8 + h0 + 1] = pdA[1];
            }
            if (row + 8 < n_rows) {
                g_as1[(row + 8) * 8 + h0]     = psB[0];
                g_as1[(row + 8) * 8 + h0 + 1] = psB[1];
                g_ad1[(row + 8) * 8 + h0]     = pdB[0];
                g_ad1[(row + 8) * 8 + h0 + 1] = pdB[1];
            }
        }
    }
}

// ---------------- agg1: single-pass softmax-aggregate, + bias + ELU --------
__global__ void agg1_kernel(const float* __restrict__ b1, int nn) {
    int warp = (blockIdx.x * 256 + threadIdx.x) >> 5;
    int lane = threadIdx.x & 31;
    if (warp >= nn) return;
    int n = warp;
    int s0 = g_off[n], s1 = g_off[n + 1];
    int hme = lane >> 2;
    float adh = __ldg(g_ad1 + n * 8 + hme);

    float4 acc = make_float4(0.f, 0.f, 0.f, 0.f);
    float4 acc2 = make_float4(0.f, 0.f, 0.f, 0.f);
    float z = 0.f, z2 = 0.f;
    int i = s0;
    for (; i + 2 <= s1; i += 2) {
        int sA = g_csr[i], sB = g_csr[i + 1];
        float aA = __ldg(g_as1 + sA * 8 + hme);
        float aB = __ldg(g_as1 + sB * 8 + hme);
        uint2 hA = *(const uint2*)(g_h1preh + (size_t)sA * HC + lane * 4);
        uint2 hB = *(const uint2*)(g_h1preh + (size_t)sB * HC + lane * 4);
        float tA = aA + adh, tB = aB + adh;
        float wA = __expf(fmaxf(tA, 0.2f * tA));
        float wB = __expf(fmaxf(tB, 0.2f * tB));
        z += wA; z2 += wB;
        float2 a01 = __half22float2(*(__half2*)&hA.x);
        float2 a23 = __half22float2(*(__half2*)&hA.y);
        float2 b01 = __half22float2(*(__half2*)&hB.x);
        float2 b23 = __half22float2(*(__half2*)&hB.y);
        acc.x += wA * a01.x;  acc.y += wA * a01.y;
        acc.z += wA * a23.x;  acc.w += wA * a23.y;
        acc2.x += wB * b01.x; acc2.y += wB * b01.y;
        acc2.z += wB * b23.x; acc2.w += wB * b23.y;
    }
    if (i < s1) {
        int s = g_csr[i];
        float av = __ldg(g_as1 + s * 8 + hme);
        uint2 hv = *(const uint2*)(g_h1preh + (size_t)s * HC + lane * 4);
        float tt = av + adh;
        float w = __expf(fmaxf(tt, 0.2f * tt));
        z += w;
        float2 a01 = __half22float2(*(__half2*)&hv.x);
        float2 a23 = __half22float2(*(__half2*)&hv.y);
        acc.x += w * a01.x; acc.y += w * a01.y;
        acc.z += w * a23.x; acc.w += w * a23.y;
    }
    float izh = 1.f / (z + z2);
    acc.x = (acc.x + acc2.x) * izh;
    acc.y = (acc.y + acc2.y) * izh;
    acc.z = (acc.z + acc2.z) * izh;
    acc.w = (acc.w + acc2.w) * izh;

    float4 bb = *(const float4*)(b1 + lane * 4);
    float t0 = acc.x + bb.x, t1 = acc.y + bb.y, t2 = acc.z + bb.z, t3 = acc.w + bb.w;
    float4 o;
    o.x = (t0 > 0.f) ? t0 : expm1f(t0);
    o.y = (t1 > 0.f) ? t1 : expm1f(t1);
    o.z = (t2 > 0.f) ? t2 : expm1f(t2);
    o.w = (t3 > 0.f) ? t3 : expm1f(t3);
    *(float4*)(g_h1 + (size_t)n * HC + lane * 4) = o;
}

// ---------------- gemm2 + att2: h2pre = h1 @ W2, a_s2, a_d2 ----------------
__global__ void gemm2_kernel(const float* __restrict__ W2,
                             const float* __restrict__ as2w,
                             const float* __restrict__ ad2w, int nn) {
    __shared__ float sW[HC * NCLS];
    __shared__ float sas[NCLS], sad[NCLS];
    for (int i = threadIdx.x; i < HC * NCLS; i += 256) sW[i] = W2[i];
    if (threadIdx.x < NCLS) {
        sas[threadIdx.x] = as2w[threadIdx.x];
        sad[threadIdx.x] = ad2w[threadIdx.x];
    }
    __syncthreads();
    int warp = (blockIdx.x * 256 + threadIdx.x) >> 5;
    int lane = threadIdx.x & 31;
    if (warp >= nn) return;
    float4 v = *(const float4*)(g_h1 + (size_t)warp * HC + lane * 4);
    float p[NCLS];
    #pragma unroll
    for (int j = 0; j < NCLS; j++) {
        int c = lane * 4;
        p[j] = v.x * sW[(c + 0) * NCLS + j] + v.y * sW[(c + 1) * NCLS + j] +
               v.z * sW[(c + 2) * NCLS + j] + v.w * sW[(c + 3) * NCLS + j];
    }
    #pragma unroll
    for (int d = 16; d; d >>= 1) {
        #pragma unroll
        for (int j = 0; j < NCLS; j++) p[j] += __shfl_xor_sync(FULLMASK, p[j], d);
    }
    if (lane == 0) {
        float s = 0.f, dd = 0.f;
        #pragma unroll
        for (int j = 0; j < NCLS; j++) {
            g_h2pre[warp * 8 + j] = p[j];
            s += p[j] * sas[j];
            dd += p[j] * sad[j];
        }
        g_h2pre[warp * 8 + 7] = 0.f;
        g_as2[warp] = s;
        g_ad2[warp] = dd;
    }
}

// ---------------- agg2: softmax-aggregate layer 2 -> output ----------------
__global__ void agg2_kernel(const float* __restrict__ b2, float* __restrict__ out,
                            int nn) {
    int warp = (blockIdx.x * 256 + threadIdx.x) >> 5;
    int lane = threadIdx.x & 31;
    if (warp >= nn) return;
    int n = warp;
    int s0 = g_off[n], s1 = g_off[n + 1];
    float adn = g_ad2[n];

    float acc[8];
    #pragma unroll
    for (int j = 0; j < 8; j++) acc[j] = 0.f;
    float z = 0.f;
    for (int i = s0 + lane; i < s1; i += 32) {
        int s = g_csr[i];
        float t = g_as2[s] + adn;
        float e = fmaxf(t, 0.2f * t);
        float w = __expf(e);
        z += w;
        float4 v0 = *(const float4*)(g_h2pre + s * 8);
        float4 v1 = *(const float4*)(g_h2pre + s * 8 + 4);
        acc[0] += w * v0.x; acc[1] += w * v0.y;
        acc[2] += w * v0.z; acc[3] += w * v0.w;
        acc[4] += w * v1.x; acc[5] += w * v1.y;
        acc[6] += w * v1.z;
    }
    #pragma unroll
    for (int d = 16; d; d >>= 1) {
        z += __shfl_xor_sync(FULLMASK, z, d);
        #pragma unroll
        for (int j = 0; j < NCLS; j++) acc[j] += __shfl_xor_sync(FULLMASK, acc[j], d);
    }
    if (lane == 0) {
        float iz = 1.f / z;
        #pragma unroll
        for (int j = 0; j < NCLS; j++) out[n * NCLS + j] = acc[j] * iz + b2[j];
    }
}

// ---------------- launch ----------------
extern "C" void kernel_launch(void* const* d_in, const int* in_sizes, int n_in,
                              void* d_out, int out_size) {
    const float* x    = (const float*)d_in[0];
    const int*   ei   = (const int*)d_in[1];     // int32 (JAX x64 disabled)
    const float* W1   = (const float*)d_in[2];
    const float* as1w = (const float*)d_in[3];
    const float* ad1w = (const float*)d_in[4];
    const float* b1   = (const float*)d_in[5];
    const float* W2   = (const float*)d_in[6];
    const float* as2w = (const float*)d_in[7];
    const float* ad2w = (const float*)d_in[8];
    const float* b2   = (const float*)d_in[9];
    float* out = (float*)d_out;

    int nn = in_sizes[0] / F_IN;   // 50000
    int E  = in_sizes[1] / 2;      // 1600000
    int NB = (nn + 1023) / 1024;

    // One-time infra (streams/events only; no device memory). Every call
    // issues the identical launch DAG, so capture/replay are deterministic.
    static cudaStream_t s_side = nullptr;
    static cudaEvent_t ev_fork = nullptr, ev_join = nullptr;
    if (s_side == nullptr) {
        cudaStreamCreateWithFlags(&s_side, cudaStreamNonBlocking);
        cudaEventCreateWithFlags(&ev_fork, cudaEventDisableTiming);
        cudaEventCreateWithFlags(&ev_join, cudaEventDisableTiming);
    }

    // fork: CSR chain on side stream, GEMM path on main (capture) stream
    cudaEventRecord(ev_fork, 0);
    cudaStreamWaitEvent(s_side, ev_fork, 0);

    deg_init_kernel<<<(nn + 255) / 256, 256, 0, s_side>>>(nn);
    deg_count_kernel<<<((E + 15) / 16 + 255) / 256, 256, 0, s_side>>>(ei, E, nn);
    scan1_kernel<<<NB, 1024, 0, s_side>>>(nn);
    scan2_kernel<<<1, 64, 0, s_side>>>(NB);
    scan3_kernel<<<(nn + 255) / 256, 256, 0, s_side>>>(nn);
    scatter_kernel<<<(E + nn + 255) / 256, 256, 0, s_side>>>(ei, E, nn);
    cudaEventRecord(ev_join, s_side);

    prep_w_kernel<<<(HC * KPAD + 255) / 256, 256>>>(W1);
    cudaFuncSetAttribute(gemm1_kernel, cudaFuncAttributeMaxDynamicSharedMemorySize,
                         GEMM1_SMEM);
    gemm1_kernel<<<(nn + 127) / 128, 256, GEMM1_SMEM>>>(x, as1w, ad1w, nn);

    // join before consumers of both CSR and gemm1 outputs
    cudaStreamWaitEvent(0, ev_join, 0);

    int wblocks = (nn * 32 + 255) / 256;
    agg1_kernel<<<wblocks, 256>>>(b1, nn);
    gemm2_kernel<<<wblocks, 256>>>(W2, as2w, ad2w, nn);
    agg2_kernel<<<wblocks, 256>>>(b2, out, nn);
}

// round 12
// speedup vs baseline: 2.4365x; 1.0335x over previous
#include <cuda_runtime.h>
#include <cuda_fp16.h>

#define FULLMASK 0xffffffffu

// ---------------- problem constants ----------------
#define F_IN   1433
#define HC     128          // HEADS*HID
#define NMAXN  50000
#define EMAXE  1600000
#define KPAD   1440         // 45 * 32
#define NCHUNK 45
#define NCLS   7

// ---------------- device scratch ----------------
__device__ __half g_h1preh[NMAXN * HC];        // x @ W1, fp16
__device__ float g_as1[NMAXN * 8];
__device__ float g_ad1[NMAXN * 8];
__device__ float g_h2pre[NMAXN * 8];           // h1 @ W2, padded stride 8
__device__ float g_as2[NMAXN];
__device__ float g_ad2[NMAXN];
__device__ int   g_deg[NMAXN];
__device__ int   g_off[NMAXN + 1];
__device__ int   g_cur[NMAXN];
__device__ int   g_csr[EMAXE + NMAXN];
__device__ int   g_bsum[64];
__device__ int   g_boff[64];
__device__ __half g_Wh[HC * KPAD];             // W1^T, [n][k], fp16

// ---------------- helpers ----------------
__device__ __forceinline__ void mma16816(float* c, const unsigned* a, const unsigned* b) {
    asm volatile(
        "mma.sync.aligned.m16n8k16.row.col.f32.f16.f16.f32 "
        "{%0,%1,%2,%3}, {%4,%5,%6,%7}, {%8,%9}, {%0,%1,%2,%3};"
        : "+f"(c[0]), "+f"(c[1]), "+f"(c[2]), "+f"(c[3])
        : "r"(a[0]), "r"(a[1]), "r"(a[2]), "r"(a[3]), "r"(b[0]), "r"(b[1]));
}

__device__ __forceinline__ unsigned smem_u32(const void* p) {
    unsigned a;
    asm("{ .reg .u64 t; cvta.to.shared.u64 t, %1; cvt.u32.u64 %0, t; }"
        : "=r"(a) : "l"(p));
    return a;
}

__device__ __forceinline__ void cp_async16(unsigned saddr, const void* gaddr) {
    asm volatile("cp.async.cg.shared.global [%0], [%1], 16;"
                 :: "r"(saddr), "l"(gaddr));
}
#define CP_COMMIT() asm volatile("cp.async.commit_group;" ::: "memory")
#define CP_WAIT0()  asm volatile("cp.async.wait_group 0;" ::: "memory")

__device__ __forceinline__ unsigned pack_h2(float lo, float hi) {
    __half2 h = __floats2half2_rn(lo, hi);
    return *reinterpret_cast<unsigned*>(&h);
}

// ---------------- prep: transpose W1 -> fp16 ----------------
__global__ void prep_w_kernel(const float* __restrict__ W1) {
    int idx = blockIdx.x * 256 + threadIdx.x;
    if (idx >= HC * KPAD) return;
    int n = idx / KPAD;
    int k = idx - n * KPAD;
    float v = (k < F_IN) ? W1[k * HC + n] : 0.f;
    g_Wh[idx] = __float2half_rn(v);
}

// ---------------- CSR build (edge_index is int32) ----------
__global__ void deg_init_kernel(int nn) {
    int t = blockIdx.x * 256 + threadIdx.x;
    if (t < nn) g_deg[t] = 1;  // self loop
}

__global__ void deg_count_kernel(const int* __restrict__ ei, int E, int nn) {
    int t = blockIdx.x * 256 + threadIdx.x;
    int base = t * 16;
    if (base + 15 < E) {
        #pragma unroll
        for (int j = 0; j < 4; j++) {
            int4 d = *(const int4*)(ei + E + base + j * 4);
            if ((unsigned)d.x < (unsigned)nn) atomicAdd(&g_deg[d.x], 1);
            if ((unsigned)d.y < (unsigned)nn) atomicAdd(&g_deg[d.y], 1);
            if ((unsigned)d.z < (unsigned)nn) atomicAdd(&g_deg[d.z], 1);
            if ((unsigned)d.w < (unsigned)nn) atomicAdd(&g_deg[d.w], 1);
        }
    } else {
        for (int i = base; i < E; i++) {
            int dst = ei[E + i];
            if ((unsigned)dst < (unsigned)nn) atomicAdd(&g_deg[dst], 1);
        }
    }
}

__global__ void scan1_kernel(int nn) {
    int b = blockIdx.x;
    int t = threadIdx.x;
    int idx = b * 1024 + t;
    int v = (idx < nn) ? g_deg[idx] : 0;
    int lane = t & 31, w = t >> 5;
    int s = v;
    #pragma unroll
    for (int d = 1; d < 32; d <<= 1) {
        int u = __shfl_up_sync(FULLMASK, s, d);
        if (lane >= d) s += u;
    }
    __shared__ int ws[32];
    if (lane == 31) ws[w] = s;
    __syncthreads();
    if (w == 0) {
        int x2 = ws[lane];
        #pragma unroll
        for (int d = 1; d < 32; d <<= 1) {
            int u = __shfl_up_sync(FULLMASK, x2, d);
            if (lane >= d) x2 += u;
        }
        ws[lane] = x2;
    }
    __syncthreads();
    int incl = s + ((w > 0) ? ws[w - 1] : 0);
    if (idx < nn) g_off[idx + 1] = incl;
    if (t == 1023) g_bsum[b] = incl;
}

__global__ void scan2_kernel(int nb) {
    int t = threadIdx.x;
    int v = (t < nb) ? g_bsum[t] : 0;
    int lane = t & 31, w = t >> 5;
    int s = v;
    #pragma unroll
    for (int d = 1; d < 32; d <<= 1) {
        int u = __shfl_up_sync(FULLMASK, s, d);
        if (lane >= d) s += u;
    }
    __shared__ int ws0;
    if (w == 0 && lane == 31) ws0 = s;
    __syncthreads();
    if (w == 1) s += ws0;
    if (t < 64) g_boff[t] = s - v;   // exclusive
}

__global__ void scan3_kernel(int nn) {
    int idx = blockIdx.x * 256 + threadIdx.x;
    if (idx >= nn) return;
    int add = g_boff[idx >> 10];
    int o = g_off[idx + 1] + add;
    g_off[idx + 1] = o;
    g_cur[idx] = o - g_deg[idx];
    if (idx == 0) g_off[0] = 0;
}

__global__ void scatter_kernel(const int* __restrict__ ei, int E, int nn) {
    int t = blockIdx.x * 256 + threadIdx.x;
    if (t < E) {
        int src = ei[t];
        int dst = ei[E + t];
        if ((unsigned)dst < (unsigned)nn && (unsigned)src < (unsigned)nn) {
            int pos = atomicAdd(&g_cur[dst], 1);
            g_csr[pos] = src;
        }
    } else if (t < E + nn) {
        int n = t - E;
        int pos = atomicAdd(&g_cur[n], 1);
        g_csr[pos] = n;
    }
}

// ---------------- GEMM1: h1pre = x @ W1 (fp16 HMMA, 64x128 tile, 3 CTA/SM) -
// CTA tile 64x128, K-chunk 32. 8 warps, each 32x32 (warp grid 2Mx4N).
// smem rows 40 halves (80B). A stage 5120 B x2 @ 0, B stage 10240 B x2 @ 10240.
#define SROWH  40
#define AST    5120
#define BST    10240
#define GEMM1_SMEM 30720

__global__ void __launch_bounds__(256, 3) gemm1_kernel(
        const float* __restrict__ x,
        const float* __restrict__ att_s, const float* __restrict__ att_d,
        int n_rows) {
    extern __shared__ char smem[];
    unsigned sb = smem_u32(smem);

    int tid = threadIdx.x;
    int lane = tid & 31;
    int wid = tid >> 5;
    int m0 = blockIdx.x * 64;
    int mw = (wid & 1) * 32;
    int nw = (wid >> 1) * 32;
    int g = lane >> 2;
    int t4 = lane & 3;

    float acc[2][4][4];
    #pragma unroll
    for (int mi = 0; mi < 2; mi++)
        #pragma unroll
        for (int ni = 0; ni < 4; ni++)
            #pragma unroll
            for (int q = 0; q < 4; q++) acc[mi][ni][q] = 0.f;

    float xa[8];
    int rA = tid >> 4;              // 0..15
    int c2A = (tid & 15) * 2;
    int gmA = m0 + rA;
    bool rvA = gmA < n_rows;
    const float* xrow = x + (size_t)gmA * F_IN;

    auto loadA = [&](int ch) {
        int k0 = ch * 32;
        #pragma unroll
        for (int i = 0; i < 4; i++) {
            int gk = k0 + c2A;
            const float* xp = xrow + (size_t)i * 16 * F_IN + gk;
            bool rv = rvA && (gmA + i * 16 < n_rows);
            xa[2 * i]     = (rv && gk < F_IN)     ? __ldg(xp)     : 0.f;
            xa[2 * i + 1] = (rv && gk + 1 < F_IN) ? __ldg(xp + 1) : 0.f;
        }
    };
    auto convA = [&](int st) {
        char* dst = smem + st * AST;
        #pragma unroll
        for (int i = 0; i < 4; i++) {
            int r = rA + i * 16;
            unsigned hp = pack_h2(xa[2 * i], xa[2 * i + 1]);
            *(unsigned*)(dst + (unsigned)(r * 80 + c2A * 2)) = hp;
        }
    };
    auto loadB = [&](int st, int ch) {
        unsigned base = sb + 10240 + st * BST;
        int k0 = ch * 32;
        #pragma unroll
        for (int j = 0; j < 2; j++) {
            int s = tid + 256 * j;       // 0..511
            int r = s >> 2;
            int q = s & 3;
            cp_async16(base + (unsigned)(r * 80 + q * 16),
                       g_Wh + (size_t)r * KPAD + k0 + q * 8);
        }
        CP_COMMIT();
    };

    loadA(0);
    convA(0);
    loadB(0, 0);
    loadA(1);

    for (int ch = 0; ch < NCHUNK; ch++) {
        int st = ch & 1;
        CP_WAIT0();
        __syncthreads();

        if (ch + 1 < NCHUNK) loadB(st ^ 1, ch + 1);

        const __half* pA = (const __half*)(smem + st * AST);
        const __half* pB = (const __half*)(smem + 10240 + st * BST);

        #pragma unroll
        for (int kk = 0; kk < 2; kk++) {
            int kc = kk * 16 + t4 * 2;
            unsigned bh[4][2];
            #pragma unroll
            for (int ni = 0; ni < 4; ni++) {
                int bn = nw + ni * 8 + g;
                bh[ni][0] = *(const unsigned*)&pB[bn * SROWH + kc];
                bh[ni][1] = *(const unsigned*)&pB[bn * SROWH + kc + 8];
            }
            #pragma unroll
            for (int mi = 0; mi < 2; mi++) {
                int ar = mw + mi * 16 + g;
                unsigned ah[4];
                ah[0] = *(const unsigned*)&pA[ar * SROWH + kc];
                ah[1] = *(const unsigned*)&pA[(ar + 8) * SROWH + kc];
                ah[2] = *(const unsigned*)&pA[ar * SROWH + kc + 8];
                ah[3] = *(const unsigned*)&pA[(ar + 8) * SROWH + kc + 8];
                #pragma unroll
                for (int ni = 0; ni < 4; ni++)
                    mma16816(acc[mi][ni], ah, bh[ni]);
            }
        }

        if (ch + 1 < NCHUNK) {
            convA(st ^ 1);
            if (ch + 2 < NCHUNK) loadA(ch + 2);
        }
    }

    // ---- epilogue: store h1pre (fp16) + fused att dots ----
    float2 asv[4], adv[4];
    #pragma unroll
    for (int ni = 0; ni < 4; ni++) {
        int c = nw + ni * 8 + t4 * 2;
        asv[ni] = *(const float2*)(att_s + c);
        adv[ni] = *(const float2*)(att_d + c);
    }
    int h0 = nw >> 4;

    #pragma unroll
    for (int mi = 0; mi < 2; mi++) {
        int row = m0 + mw + mi * 16 + g;
        #pragma unroll
        for (int ni = 0; ni < 4; ni++) {
            int col = nw + ni * 8 + t4 * 2;
            if (row < n_rows) {
                unsigned hp = pack_h2(acc[mi][ni][0], acc[mi][ni][1]);
                *(unsigned*)(g_h1preh + (size_t)row * HC + col) = hp;
            }
            if (row + 8 < n_rows) {
                unsigned hp = pack_h2(acc[mi][ni][2], acc[mi][ni][3]);
                *(unsigned*)(g_h1preh + (size_t)(row + 8) * HC + col) = hp;
            }
        }
        float psA[2] = {0.f, 0.f}, psB[2] = {0.f, 0.f};
        float pdA[2] = {0.f, 0.f}, pdB[2] = {0.f, 0.f};
        #pragma unroll
        for (int ni = 0; ni < 4; ni++) {
            int hh = ni >> 1;
            psA[hh] += acc[mi][ni][0] * asv[ni].x + acc[mi][ni][1] * asv[ni].y;
            psB[hh] += acc[mi][ni][2] * asv[ni].x + acc[mi][ni][3] * asv[ni].y;
            pdA[hh] += acc[mi][ni][0] * adv[ni].x + acc[mi][ni][1] * adv[ni].y;
            pdB[hh] += acc[mi][ni][2] * adv[ni].x + acc[mi][ni][3] * adv[ni].y;
        }
        #pragma unroll
        for (int hh = 0; hh < 2; hh++) {
            psA[hh] += __shfl_xor_sync(FULLMASK, psA[hh], 1);
            psA[hh] += __shfl_xor_sync(FULLMASK, psA[hh], 2);
            psB[hh] += __shfl_xor_sync(FULLMASK, psB[hh], 1);
            psB[hh] += __shfl_xor_sync(FULLMASK, psB[hh], 2);
            pdA[hh] += __shfl_xor_sync(FULLMASK, pdA[hh], 1);
            pdA[hh] += __shfl_xor_sync(FULLMASK, pdA[hh], 2);
            pdB[hh] += __shfl_xor_sync(FULLMASK, pdB[hh], 1);
            pdB[hh] += __shfl_xor_sync(FULLMASK, pdB[hh], 2);
        }
        if (t4 == 0) {
            if (row < n_rows) {
                g_as1[row * 8 + h0]     = psA[0];
                g_as1[row * 8 + h0 + 1] = psA[1];
                g_ad1[row * 8 + h0]     = pdA[0];
                g_ad1[row * 8 + h0 + 1] = pdA[1];
            }
            if (row + 8 < n_rows) {
                g_as1[(row + 8) * 8 + h0]     = psB[0];
                g_as1[(row + 8) * 8 + h0 + 1] = psB[1];
                g_ad1[(row + 8) * 8 + h0]     = pdB[0];
                g_ad1[(row + 8) * 8 + h0 + 1] = pdB[1];
            }
        }
    }
}

// ---------------- agg1 (+ fused gemm2/att2): softmax-agg -> h2pre/as2/ad2 --
__global__ void agg1_kernel(const float* __restrict__ b1,
                            const float* __restrict__ W2,
                            const float* __restrict__ as2w,
                            const float* __restrict__ ad2w, int nn) {
    __shared__ float sW[HC * NCLS];
    __shared__ float sas[NCLS], sad[NCLS];
    for (int i = threadIdx.x; i < HC * NCLS; i += 256) sW[i] = W2[i];
    if (threadIdx.x < NCLS) {
        sas[threadIdx.x] = as2w[threadIdx.x];
        sad[threadIdx.x] = ad2w[threadIdx.x];
    }
    __syncthreads();

    int warp = (blockIdx.x * 256 + threadIdx.x) >> 5;
    int lane = threadIdx.x & 31;
    if (warp >= nn) return;
    int n = warp;
    int s0 = g_off[n], s1 = g_off[n + 1];
    int hme = lane >> 2;
    float adh = __ldg(g_ad1 + n * 8 + hme);

    float4 acc = make_float4(0.f, 0.f, 0.f, 0.f);
    float4 acc2 = make_float4(0.f, 0.f, 0.f, 0.f);
    float z = 0.f, z2 = 0.f;
    int i = s0;
    for (; i + 2 <= s1; i += 2) {
        int sA = g_csr[i], sB = g_csr[i + 1];
        float aA = __ldg(g_as1 + sA * 8 + hme);
        float aB = __ldg(g_as1 + sB * 8 + hme);
        uint2 hA = *(const uint2*)(g_h1preh + (size_t)sA * HC + lane * 4);
        uint2 hB = *(const uint2*)(g_h1preh + (size_t)sB * HC + lane * 4);
        float tA = aA + adh, tB = aB + adh;
        float wA = __expf(fmaxf(tA, 0.2f * tA));
        float wB = __expf(fmaxf(tB, 0.2f * tB));
        z += wA; z2 += wB;
        float2 a01 = __half22float2(*(__half2*)&hA.x);
        float2 a23 = __half22float2(*(__half2*)&hA.y);
        float2 b01 = __half22float2(*(__half2*)&hB.x);
        float2 b23 = __half22float2(*(__half2*)&hB.y);
        acc.x += wA * a01.x;  acc.y += wA * a01.y;
        acc.z += wA * a23.x;  acc.w += wA * a23.y;
        acc2.x += wB * b01.x; acc2.y += wB * b01.y;
        acc2.z += wB * b23.x; acc2.w += wB * b23.y;
    }
    if (i < s1) {
        int s = g_csr[i];
        float av = __ldg(g_as1 + s * 8 + hme);
        uint2 hv = *(const uint2*)(g_h1preh + (size_t)s * HC + lane * 4);
        float tt = av + adh;
        float w = __expf(fmaxf(tt, 0.2f * tt));
        z += w;
        float2 a01 = __half22float2(*(__half2*)&hv.x);
        float2 a23 = __half22float2(*(__half2*)&hv.y);
        acc.x += w * a01.x; acc.y += w * a01.y;
        acc.z += w * a23.x; acc.w += w * a23.y;
    }
    float izh = 1.f / (z + z2);
    acc.x = (acc.x + acc2.x) * izh;
    acc.y = (acc.y + acc2.y) * izh;
    acc.z = (acc.z + acc2.z) * izh;
    acc.w = (acc.w + acc2.w) * izh;

    float4 bb = *(const float4*)(b1 + lane * 4);
    float t0 = acc.x + bb.x, t1 = acc.y + bb.y, t2 = acc.z + bb.z, t3 = acc.w + bb.w;
    float o0 = (t0 > 0.f) ? t0 : expm1f(t0);
    float o1 = (t1 > 0.f) ? t1 : expm1f(t1);
    float o2 = (t2 > 0.f) ? t2 : expm1f(t2);
    float o3 = (t3 > 0.f) ? t3 : expm1f(t3);

    // fused gemm2: lane holds h1 dims c..c+3; contract with W2 and reduce
    int c = lane * 4;
    float p[NCLS];
    #pragma unroll
    for (int j = 0; j < NCLS; j++) {
        p[j] = o0 * sW[(c + 0) * NCLS + j] + o1 * sW[(c + 1) * NCLS + j] +
               o2 * sW[(c + 2) * NCLS + j] + o3 * sW[(c + 3) * NCLS + j];
    }
    #pragma unroll
    for (int d = 16; d; d >>= 1) {
        #pragma unroll
        for (int j = 0; j < NCLS; j++) p[j] += __shfl_xor_sync(FULLMASK, p[j], d);
    }
    if (lane == 0) {
        float s = 0.f, dd = 0.f;
        #pragma unroll
        for (int j = 0; j < NCLS; j++) {
            g_h2pre[n * 8 + j] = p[j];
            s += p[j] * sas[j];
            dd += p[j] * sad[j];
        }
        g_h2pre[n * 8 + 7] = 0.f;
        g_as2[n] = s;
        g_ad2[n] = dd;
    }
}

// ---------------- agg2: softmax-aggregate layer 2 -> output ----------------
__global__ void agg2_kernel(const float* __restrict__ b2, float* __restrict__ out,
                            int nn) {
    int warp = (blockIdx.x * 256 + threadIdx.x) >> 5;
    int lane = threadIdx.x & 31;
    if (warp >= nn) return;
    int n = warp;
    int s0 = g_off[n], s1 = g_off[n + 1];
    float adn = g_ad2[n];

    float acc[8];
    #pragma unroll
    for (int j = 0; j < 8; j++) acc[j] = 0.f;
    float z = 0.f;
    for (int i = s0 + lane; i < s1; i += 32) {
        int s = g_csr[i];
        float t = g_as2[s] + adn;
        float e = fmaxf(t, 0.2f * t);
        float w = __expf(e);
        z += w;
        float4 v0 = *(const float4*)(g_h2pre + s * 8);
        float4 v1 = *(const float4*)(g_h2pre + s * 8 + 4);
        acc[0] += w * v0.x; acc[1] += w * v0.y;
        acc[2] += w * v0.z; acc[3] += w * v0.w;
        acc[4] += w * v1.x; acc[5] += w * v1.y;
        acc[6] += w * v1.z;
    }
    #pragma unroll
    for (int d = 16; d; d >>= 1) {
        z += __shfl_xor_sync(FULLMASK, z, d);
        #pragma unroll
        for (int j = 0; j < NCLS; j++) acc[j] += __shfl_xor_sync(FULLMASK, acc[j], d);
    }
    if (lane == 0) {
        float iz = 1.f / z;
        #pragma unroll
        for (int j = 0; j < NCLS; j++) out[n * NCLS + j] = acc[j] * iz + b2[j];
    }
}

// ---------------- launch ----------------
extern "C" void kernel_launch(void* const* d_in, const int* in_sizes, int n_in,
                              void* d_out, int out_size) {
    const float* x    = (const float*)d_in[0];
    const int*   ei   = (const int*)d_in[1];     // int32 (JAX x64 disabled)
    const float* W1   = (const float*)d_in[2];
    const float* as1w = (const float*)d_in[3];
    const float* ad1w = (const float*)d_in[4];
    const float* b1   = (const float*)d_in[5];
    const float* W2   = (const float*)d_in[6];
    const float* as2w = (const float*)d_in[7];
    const float* ad2w = (const float*)d_in[8];
    const float* b2   = (const float*)d_in[9];
    float* out = (float*)d_out;

    int nn = in_sizes[0] / F_IN;   // 50000
    int E  = in_sizes[1] / 2;      // 1600000
    int NB = (nn + 1023) / 1024;

    static cudaStream_t s_side = nullptr;
    static cudaEvent_t ev_fork = nullptr, ev_join = nullptr;
    if (s_side == nullptr) {
        cudaStreamCreateWithFlags(&s_side, cudaStreamNonBlocking);
        cudaEventCreateWithFlags(&ev_fork, cudaEventDisableTiming);
        cudaEventCreateWithFlags(&ev_join, cudaEventDisableTiming);
    }

    // fork: CSR chain on side stream, GEMM path on main (capture) stream
    cudaEventRecord(ev_fork, 0);
    cudaStreamWaitEvent(s_side, ev_fork, 0);

    deg_init_kernel<<<(nn + 255) / 256, 256, 0, s_side>>>(nn);
    deg_count_kernel<<<((E + 15) / 16 + 255) / 256, 256, 0, s_side>>>(ei, E, nn);
    scan1_kernel<<<NB, 1024, 0, s_side>>>(nn);
    scan2_kernel<<<1, 64, 0, s_side>>>(NB);
    scan3_kernel<<<(nn + 255) / 256, 256, 0, s_side>>>(nn);
    scatter_kernel<<<(E + nn + 255) / 256, 256, 0, s_side>>>(ei, E, nn);
    cudaEventRecord(ev_join, s_side);

    prep_w_kernel<<<(HC * KPAD + 255) / 256, 256>>>(W1);
    cudaFuncSetAttribute(gemm1_kernel, cudaFuncAttributeMaxDynamicSharedMemorySize,
                         GEMM1_SMEM);
    gemm1_kernel<<<(nn + 63) / 64, 256, GEMM1_SMEM>>>(x, as1w, ad1w, nn);

    cudaStreamWaitEvent(0, ev_join, 0);

    int wblocks = (nn * 32 + 255) / 256;
    agg1_kernel<<<wblocks, 256>>>(b1, W2, as2w, ad2w, nn);
    agg2_kernel<<<wblocks, 256>>>(b2, out, nn);
}